// round 1
// baseline (speedup 1.0000x reference)
#include <cuda_runtime.h>
#include <math.h>

// ---------------------------------------------------------------------------
// Problem constants
// ---------------------------------------------------------------------------
#define NN 4096          // nodes
#define DIN 256          // input dim
#define ED 512           // quantum dim
#define NHEAD 8
#define HD 64
#define MASKW 128        // 4096/32 words per row

#define NEG_INF (__int_as_float(0xff800000))

// ---------------------------------------------------------------------------
// Scratch (device globals; no allocation allowed)
// ---------------------------------------------------------------------------
__device__ float    g_Q0[(size_t)NN * ED];
__device__ float    g_K0[(size_t)NN * ED];
__device__ float    g_QKV[(size_t)3 * NN * ED];   // Qfinal, Kfinal, V (contiguous for batched in_proj)
__device__ float    g_qkv2[(size_t)3 * NN * ED];  // q, k, v after in_proj
__device__ float    g_o[(size_t)NN * ED];
__device__ float    g_bioT[(size_t)ED * ED];
__device__ unsigned g_mask[(size_t)NN * MASKW];
__device__ float    g_rowent[NN];

// ---------------------------------------------------------------------------
// Warp reduction helpers
// ---------------------------------------------------------------------------
__device__ __forceinline__ float warp_red_sum(float v) {
#pragma unroll
    for (int o = 16; o; o >>= 1) v += __shfl_xor_sync(0xffffffffu, v, o);
    return v;
}
__device__ __forceinline__ float warp_red_max(float v) {
#pragma unroll
    for (int o = 16; o; o >>= 1) v = fmaxf(v, __shfl_xor_sync(0xffffffffu, v, o));
    return v;
}
__device__ __forceinline__ float red16_max(float v) {
    v = fmaxf(v, __shfl_xor_sync(0xffffffffu, v, 8));
    v = fmaxf(v, __shfl_xor_sync(0xffffffffu, v, 4));
    v = fmaxf(v, __shfl_xor_sync(0xffffffffu, v, 2));
    v = fmaxf(v, __shfl_xor_sync(0xffffffffu, v, 1));
    return v;
}
__device__ __forceinline__ float red16_sum(float v) {
    v += __shfl_xor_sync(0xffffffffu, v, 8);
    v += __shfl_xor_sync(0xffffffffu, v, 4);
    v += __shfl_xor_sync(0xffffffffu, v, 2);
    v += __shfl_xor_sync(0xffffffffu, v, 1);
    return v;
}

// ---------------------------------------------------------------------------
// Mask build
// ---------------------------------------------------------------------------
__global__ void zero_mask_kernel(unsigned* __restrict__ m) {
    m[(size_t)blockIdx.x * 1024 + threadIdx.x] = 0u;
}

__global__ void build_mask_kernel(const int* __restrict__ ei, int ne,
                                  unsigned* __restrict__ m) {
    int idx = blockIdx.x * blockDim.x + threadIdx.x;
    if (idx < ne) {
        int r = ei[idx];
        int c = ei[ne + idx];
        atomicOr(&m[(size_t)r * MASKW + (c >> 5)], 1u << (c & 31));
    }
}

// ---------------------------------------------------------------------------
// 512x512 transpose (bio -> bioT)
// ---------------------------------------------------------------------------
__global__ void transpose512_kernel(const float* __restrict__ in, float* __restrict__ out) {
    __shared__ float tile[32][33];
    int bx = blockIdx.x * 32, by = blockIdx.y * 32;
    int tx = threadIdx.x, ty = threadIdx.y;
#pragma unroll
    for (int j = 0; j < 32; j += 8)
        tile[ty + j][tx] = in[(size_t)(by + ty + j) * ED + bx + tx];
    __syncthreads();
#pragma unroll
    for (int j = 0; j < 32; j += 8)
        out[(size_t)(bx + ty + j) * ED + by + tx] = tile[tx][ty + j];
}

// ---------------------------------------------------------------------------
// fp32 SGEMM (NT):  C[M,N] = A[M,K] * B[N,K]^T  (+ epilogue)
// 128x128 block tile, BK=16, 256 threads, 8x8 microtile
// ---------------------------------------------------------------------------
#define BM 128
#define BN 128
#define BK 16

enum { EPI_BIAS = 0, EPI_CE = 1, EPI_MASK = 2 };

template <int EPI>
__global__ void __launch_bounds__(256)
sgemm_nt(const float* __restrict__ A, long long sAz,
         const float* __restrict__ B, long long sBz,
         float* __restrict__ C, long long sCz,
         int M, int N, int K,
         const float* __restrict__ bias, long long sbz,
         const int* __restrict__ ct,
         const float* __restrict__ cemb,
         const unsigned* __restrict__ mask,
         float scale)
{
    A += (size_t)blockIdx.z * sAz;
    B += (size_t)blockIdx.z * sBz;
    C += (size_t)blockIdx.z * sCz;
    if (bias) bias += (size_t)blockIdx.z * sbz;

    __shared__ float As[BK][BM];
    __shared__ float Bs[BK][BN];

    const int tid = threadIdx.x;
    const int tx = tid & 15, ty = tid >> 4;
    const int bm = blockIdx.y * BM, bn = blockIdx.x * BN;

    const int lrow = tid >> 2;       // 0..63
    const int lc4  = (tid & 3) * 4;  // 0,4,8,12

    float acc[8][8];
#pragma unroll
    for (int i = 0; i < 8; ++i)
#pragma unroll
        for (int j = 0; j < 8; ++j) acc[i][j] = 0.f;

    for (int k0 = 0; k0 < K; k0 += BK) {
#pragma unroll
        for (int t = 0; t < 2; ++t) {
            int row = lrow + t * 64;
            float4 va = *(const float4*)(A + (size_t)(bm + row) * K + k0 + lc4);
            As[lc4 + 0][row] = va.x; As[lc4 + 1][row] = va.y;
            As[lc4 + 2][row] = va.z; As[lc4 + 3][row] = va.w;
            float4 vb = *(const float4*)(B + (size_t)(bn + row) * K + k0 + lc4);
            Bs[lc4 + 0][row] = vb.x; Bs[lc4 + 1][row] = vb.y;
            Bs[lc4 + 2][row] = vb.z; Bs[lc4 + 3][row] = vb.w;
        }
        __syncthreads();
#pragma unroll
        for (int kk = 0; kk < BK; ++kk) {
            float4 a0 = *(const float4*)&As[kk][ty * 8];
            float4 a1 = *(const float4*)&As[kk][ty * 8 + 4];
            float4 b0 = *(const float4*)&Bs[kk][tx * 8];
            float4 b1 = *(const float4*)&Bs[kk][tx * 8 + 4];
            float av[8] = {a0.x, a0.y, a0.z, a0.w, a1.x, a1.y, a1.z, a1.w};
            float bv[8] = {b0.x, b0.y, b0.z, b0.w, b1.x, b1.y, b1.z, b1.w};
#pragma unroll
            for (int i = 0; i < 8; ++i)
#pragma unroll
                for (int j = 0; j < 8; ++j)
                    acc[i][j] += av[i] * bv[j];
        }
        __syncthreads();
    }

#pragma unroll
    for (int i = 0; i < 8; ++i) {
        int gm = bm + ty * 8 + i;
#pragma unroll
        for (int j = 0; j < 8; ++j) {
            int gn = bn + tx * 8 + j;
            float v = acc[i][j];
            if (EPI == EPI_BIAS) {
                v += bias[gn];
            } else if (EPI == EPI_CE) {
                v += 0.1f * cemb[(size_t)ct[gm] * N + gn];
            } else {
                bool on = (mask[(size_t)gm * MASKW + (gn >> 5)] >> (gn & 31)) & 1u;
                v = on ? v * scale : -1e9f;
            }
            C[(size_t)gm * N + gn] = v;
        }
    }
}

// ---------------------------------------------------------------------------
// phase = atan2(K, Q) elementwise
// ---------------------------------------------------------------------------
__global__ void phase_kernel(const float* __restrict__ Q, const float* __restrict__ K,
                             float* __restrict__ phase) {
    size_t i = (size_t)blockIdx.x * blockDim.x + threadIdx.x;
    phase[i] = atan2f(K[i], Q[i]);
}

// ---------------------------------------------------------------------------
// Row softmax over masked scores (in-place on attn region) + per-row entropy
// one block per row, 256 threads, 16 elements/thread in registers
// ---------------------------------------------------------------------------
__global__ void __launch_bounds__(256)
softmax_row_kernel(float* __restrict__ attn, float* __restrict__ row_ent) {
    __shared__ float red[8];
    __shared__ float bval;
    const int tid = threadIdx.x;
    const int wid = tid >> 5, lane = tid & 31;
    float* p = attn + (size_t)blockIdx.x * NN;

    float4 x[4];
#pragma unroll
    for (int t = 0; t < 4; ++t)
        x[t] = *(const float4*)(p + t * 1024 + tid * 4);

    float mx = NEG_INF;
#pragma unroll
    for (int t = 0; t < 4; ++t)
        mx = fmaxf(fmaxf(fmaxf(mx, x[t].x), fmaxf(x[t].y, x[t].z)), x[t].w);
    mx = warp_red_max(mx);
    if (lane == 0) red[wid] = mx;
    __syncthreads();
    if (wid == 0) {
        float v = (lane < 8) ? red[lane] : NEG_INF;
        v = warp_red_max(v);
        if (lane == 0) bval = v;
    }
    __syncthreads();
    mx = bval;
    __syncthreads();

    float e[16];
    float s = 0.f;
#pragma unroll
    for (int t = 0; t < 4; ++t) {
        e[t * 4 + 0] = __expf(x[t].x - mx);
        e[t * 4 + 1] = __expf(x[t].y - mx);
        e[t * 4 + 2] = __expf(x[t].z - mx);
        e[t * 4 + 3] = __expf(x[t].w - mx);
        s += e[t * 4 + 0] + e[t * 4 + 1] + e[t * 4 + 2] + e[t * 4 + 3];
    }
    s = warp_red_sum(s);
    if (lane == 0) red[wid] = s;
    __syncthreads();
    if (wid == 0) {
        float v = (lane < 8) ? red[lane] : 0.f;
        v = warp_red_sum(v);
        if (lane == 0) bval = v;
    }
    __syncthreads();
    const float inv = 1.0f / bval;
    __syncthreads();

    float ent = 0.f;
#pragma unroll
    for (int t = 0; t < 4; ++t) {
        float4 r;
        r.x = e[t * 4 + 0] * inv;
        r.y = e[t * 4 + 1] * inv;
        r.z = e[t * 4 + 2] * inv;
        r.w = e[t * 4 + 3] * inv;
        ent += r.x * logf(r.x + 1e-10f) + r.y * logf(r.y + 1e-10f)
             + r.z * logf(r.z + 1e-10f) + r.w * logf(r.w + 1e-10f);
        *(float4*)(p + t * 1024 + tid * 4) = r;
    }
    ent = warp_red_sum(ent);
    if (lane == 0) red[wid] = ent;
    __syncthreads();
    if (wid == 0) {
        float v = (lane < 8) ? red[lane] : 0.f;
        v = warp_red_sum(v);
        if (lane == 0) row_ent[blockIdx.x] = v;   // sum p*log(p+eps), entropy = -sum
    }
}

__global__ void reduce_entropy_kernel(const float* __restrict__ row_ent,
                                      float* __restrict__ coh) {
    __shared__ float red[32];
    int tid = threadIdx.x, lane = tid & 31, wid = tid >> 5;
    float v = row_ent[tid] + row_ent[tid + 1024] + row_ent[tid + 2048] + row_ent[tid + 3072];
    v = warp_red_sum(v);
    if (lane == 0) red[wid] = v;
    __syncthreads();
    if (wid == 0) {
        float s = red[lane];
        s = warp_red_sum(s);
        if (lane == 0) {
            float entropy = -s;
            *coh = 1.0f - entropy / logf((float)NN);
        }
    }
}

// ---------------------------------------------------------------------------
// Flash-style MHA: softmax(q k^T / 8) v, per head.
// Block = 128 q rows x 1 head, key tiles of 64, 256 threads.
// Register microtiles: 8 rows x 4 cols per thread (SGEMM-shaped QK and PV).
// ---------------------------------------------------------------------------
#define QS_LD 132
#define KS_LD 68

__global__ void __launch_bounds__(256, 2)
flash_mha(const float* __restrict__ q, const float* __restrict__ k,
          const float* __restrict__ v, float* __restrict__ o)
{
    extern __shared__ float sm[];
    float* qs = sm;                         // [64][132]  qs[d][m]
    float* ks = qs + 64 * QS_LD;            // [64][68]   ks[d][j]
    float* vs = ks + 64 * KS_LD;            // [64][68]   vs[j][dv]
    float* ps = vs + 64 * KS_LD;            // [64][132]  ps[j][m]

    const int tid = threadIdx.x;
    const int tx = tid & 15, ty = tid >> 4;
    const int head = blockIdx.y;
    const int qbase = blockIdx.x * 128;
    const int hoff = head * HD;
    const int m0 = ty * 8;

    // load q tile transposed: qs[d][m]
#pragma unroll
    for (int t = 0; t < 8; ++t) {
        int f = tid + t * 256;              // 0..2047 float4s
        int row = f >> 4, c4 = (f & 15) * 4;
        float4 val = *(const float4*)(q + (size_t)(qbase + row) * ED + hoff + c4);
        qs[(c4 + 0) * QS_LD + row] = val.x;
        qs[(c4 + 1) * QS_LD + row] = val.y;
        qs[(c4 + 2) * QS_LD + row] = val.z;
        qs[(c4 + 3) * QS_LD + row] = val.w;
    }

    float m_i[8], l_i[8], oacc[8][4];
#pragma unroll
    for (int i = 0; i < 8; ++i) {
        m_i[i] = NEG_INF;
        l_i[i] = 0.f;
#pragma unroll
        for (int c = 0; c < 4; ++c) oacc[i][c] = 0.f;
    }

    for (int kt = 0; kt < NN / 64; ++kt) {
        __syncthreads();
        // load k transposed (ks[d][j]) and v natural (vs[j][dv])
#pragma unroll
        for (int t = 0; t < 4; ++t) {
            int f = tid + t * 256;          // 0..1023 float4s
            int row = f >> 4, c4 = (f & 15) * 4;
            float4 kv = *(const float4*)(k + (size_t)(kt * 64 + row) * ED + hoff + c4);
            ks[(c4 + 0) * KS_LD + row] = kv.x;
            ks[(c4 + 1) * KS_LD + row] = kv.y;
            ks[(c4 + 2) * KS_LD + row] = kv.z;
            ks[(c4 + 3) * KS_LD + row] = kv.w;
            float4 vv = *(const float4*)(v + (size_t)(kt * 64 + row) * ED + hoff + c4);
            *(float4*)(vs + row * KS_LD + c4) = vv;
        }
        __syncthreads();

        // S[8][4] = q k^T
        float s[8][4];
#pragma unroll
        for (int i = 0; i < 8; ++i)
#pragma unroll
            for (int c = 0; c < 4; ++c) s[i][c] = 0.f;

#pragma unroll 4
        for (int d = 0; d < HD; ++d) {
            float4 b = *(const float4*)(ks + d * KS_LD + tx * 4);
            float4 a0 = *(const float4*)(qs + d * QS_LD + m0);
            float4 a1 = *(const float4*)(qs + d * QS_LD + m0 + 4);
            float av[8] = {a0.x, a0.y, a0.z, a0.w, a1.x, a1.y, a1.z, a1.w};
            float bv[4] = {b.x, b.y, b.z, b.w};
#pragma unroll
            for (int i = 0; i < 8; ++i)
#pragma unroll
                for (int c = 0; c < 4; ++c)
                    s[i][c] += av[i] * bv[c];
        }

        // online softmax per row (row spread over 16 lanes: lanes (ty%2)*16 + tx)
#pragma unroll
        for (int i = 0; i < 8; ++i) {
#pragma unroll
            for (int c = 0; c < 4; ++c) s[i][c] *= 0.125f;   // 1/sqrt(64)
            float mx = fmaxf(fmaxf(s[i][0], s[i][1]), fmaxf(s[i][2], s[i][3]));
            mx = red16_max(mx);
            float mnew = fmaxf(m_i[i], mx);
            float corr = __expf(m_i[i] - mnew);
            m_i[i] = mnew;
            float p0 = __expf(s[i][0] - mnew);
            float p1 = __expf(s[i][1] - mnew);
            float p2 = __expf(s[i][2] - mnew);
            float p3 = __expf(s[i][3] - mnew);
            float ls = red16_sum(p0 + p1 + p2 + p3);
            l_i[i] = l_i[i] * corr + ls;
#pragma unroll
            for (int c = 0; c < 4; ++c) oacc[i][c] *= corr;
            ps[(tx * 4 + 0) * QS_LD + m0 + i] = p0;
            ps[(tx * 4 + 1) * QS_LD + m0 + i] = p1;
            ps[(tx * 4 + 2) * QS_LD + m0 + i] = p2;
            ps[(tx * 4 + 3) * QS_LD + m0 + i] = p3;
        }
        __syncwarp();   // ps producers/consumers for a row-block are the same half-warp

        // O += P V
#pragma unroll 4
        for (int j = 0; j < 64; ++j) {
            float4 b = *(const float4*)(vs + j * KS_LD + tx * 4);
            float4 a0 = *(const float4*)(ps + j * QS_LD + m0);
            float4 a1 = *(const float4*)(ps + j * QS_LD + m0 + 4);
            float av[8] = {a0.x, a0.y, a0.z, a0.w, a1.x, a1.y, a1.z, a1.w};
            float bv[4] = {b.x, b.y, b.z, b.w};
#pragma unroll
            for (int i = 0; i < 8; ++i)
#pragma unroll
                for (int c = 0; c < 4; ++c)
                    oacc[i][c] += av[i] * bv[c];
        }
        __syncwarp();
    }

    // normalize + store
#pragma unroll
    for (int i = 0; i < 8; ++i) {
        float inv = 1.0f / l_i[i];
        float4 r;
        r.x = oacc[i][0] * inv;
        r.y = oacc[i][1] * inv;
        r.z = oacc[i][2] * inv;
        r.w = oacc[i][3] * inv;
        *(float4*)(o + (size_t)(qbase + m0 + i) * ED + hoff + tx * 4) = r;
    }
}

// ---------------------------------------------------------------------------
// Host launcher
// ---------------------------------------------------------------------------
extern "C" void kernel_launch(void* const* d_in, const int* in_sizes, int n_in,
                              void* d_out, int out_size)
{
    const float* nf   = (const float*)d_in[0];
    const int*   ei   = (const int*)  d_in[1];
    const int*   ct   = (const int*)  d_in[2];
    const float* Wq   = (const float*)d_in[3];
    const float* bq   = (const float*)d_in[4];
    const float* Wk   = (const float*)d_in[5];
    const float* bk   = (const float*)d_in[6];
    const float* Wv   = (const float*)d_in[7];
    const float* bv   = (const float*)d_in[8];
    const float* bio  = (const float*)d_in[9];
    const float* cemb = (const float*)d_in[10];
    const float* ipw  = (const float*)d_in[11];
    const float* ipb  = (const float*)d_in[12];
    const float* outw = (const float*)d_in[13];
    const float* outb = (const float*)d_in[14];

    float* out      = (float*)d_out;
    float* attended = out;                                    // [4096,512]
    float* attn     = out + (size_t)NN * ED;                  // [4096,4096]
    float* phase    = attn + (size_t)NN * NN;                 // [4096,512]
    float* coh      = phase + (size_t)NN * ED;                // scalar

    const int ne = in_sizes[1] / 2;
    const size_t NS = (size_t)NN * ED;

    float *Q0, *K0, *QKV, *qkv2, *og, *bioT, *rowent;
    unsigned* msk;
    cudaGetSymbolAddress((void**)&Q0,     g_Q0);
    cudaGetSymbolAddress((void**)&K0,     g_K0);
    cudaGetSymbolAddress((void**)&QKV,    g_QKV);
    cudaGetSymbolAddress((void**)&qkv2,   g_qkv2);
    cudaGetSymbolAddress((void**)&og,     g_o);
    cudaGetSymbolAddress((void**)&bioT,   g_bioT);
    cudaGetSymbolAddress((void**)&msk,    g_mask);
    cudaGetSymbolAddress((void**)&rowent, g_rowent);

    // edge mask
    zero_mask_kernel<<<(NN * MASKW) / 1024, 1024>>>(msk);
    build_mask_kernel<<<(ne + 255) / 256, 256>>>(ei, ne, msk);

    // bio^T for Q-side mixing
    transpose512_kernel<<<dim3(16, 16), dim3(32, 8)>>>(bio, bioT);

    // Q0/K0/V projections:  X @ W^T + b   (M=4096, N=512, K=256)
    sgemm_nt<EPI_BIAS><<<dim3(4, 32), 256>>>(nf, 0, Wq, 0, Q0, 0, NN, ED, DIN,
                                             bq, 0, nullptr, nullptr, nullptr, 0.f);
    sgemm_nt<EPI_BIAS><<<dim3(4, 32), 256>>>(nf, 0, Wk, 0, K0, 0, NN, ED, DIN,
                                             bk, 0, nullptr, nullptr, nullptr, 0.f);
    sgemm_nt<EPI_BIAS><<<dim3(4, 32), 256>>>(nf, 0, Wv, 0, QKV + 2 * NS, 0, NN, ED, DIN,
                                             bv, 0, nullptr, nullptr, nullptr, 0.f);

    // bio mixing + 0.1*cell_emb:  Qf = Q0 @ bio + ce,  Kf = K0 @ bio^T + ce
    sgemm_nt<EPI_CE><<<dim3(4, 32), 256>>>(Q0, 0, bioT, 0, QKV, 0, NN, ED, ED,
                                           nullptr, 0, ct, cemb, nullptr, 0.f);
    sgemm_nt<EPI_CE><<<dim3(4, 32), 256>>>(K0, 0, bio, 0, QKV + NS, 0, NN, ED, ED,
                                           nullptr, 0, ct, cemb, nullptr, 0.f);

    // phase = atan2(Kf, Qf)
    phase_kernel<<<(NN * ED) / 1024, 1024>>>(QKV, QKV + NS, phase);

    // masked scores -> attn region:  Qf @ Kf^T / sqrt(512), -1e9 off-edge
    sgemm_nt<EPI_MASK><<<dim3(32, 32), 256>>>(QKV, 0, QKV + NS, 0, attn, 0, NN, NN, ED,
                                              nullptr, 0, nullptr, nullptr, msk,
                                              0.044194173824159216f);

    // row softmax in-place + per-row entropy, then coherence
    softmax_row_kernel<<<NN, 256>>>(attn, rowent);
    reduce_entropy_kernel<<<1, 1024>>>(rowent, coh);

    // in_proj (batched z=3): q/k/v = {Qf,Kf,V} @ ipw[z]^T + ipb[z]
    sgemm_nt<EPI_BIAS><<<dim3(4, 32, 3), 256>>>(QKV, (long long)NS,
                                                ipw, (long long)ED * ED,
                                                qkv2, (long long)NS,
                                                NN, ED, ED,
                                                ipb, (long long)ED,
                                                nullptr, nullptr, nullptr, 0.f);

    // flash MHA per head
    cudaFuncSetAttribute(flash_mha, cudaFuncAttributeMaxDynamicSharedMemorySize, 102400);
    flash_mha<<<dim3(NN / 128, NHEAD), 256, 102400>>>(qkv2, qkv2 + NS, qkv2 + 2 * NS, og);

    // output projection
    sgemm_nt<EPI_BIAS><<<dim3(4, 32), 256>>>(og, 0, outw, 0, attended, 0, NN, ED, ED,
                                             outb, 0, nullptr, nullptr, nullptr, 0.f);
}

// round 5
// speedup vs baseline: 1.1465x; 1.1465x over previous
#include <cuda_runtime.h>
#include <math.h>
#include <stdint.h>

// ---------------------------------------------------------------------------
// Problem constants
// ---------------------------------------------------------------------------
#define NN 4096          // nodes
#define DIN 256          // input dim
#define ED 512           // quantum dim
#define NHEAD 8
#define HD 64
#define MASKW 128        // 4096/32 words per row

#define NEG_INF (__int_as_float(0xff800000))

// ---------------------------------------------------------------------------
// Scratch (device globals; no allocation allowed)
// ---------------------------------------------------------------------------
__device__ float    g_Q0[(size_t)NN * ED];
__device__ float    g_K0[(size_t)NN * ED];
__device__ float    g_QKV[(size_t)3 * NN * ED];   // Qfinal, Kfinal, V
__device__ float    g_qkv2[(size_t)3 * NN * ED];  // q, k, v after in_proj
__device__ float    g_o[(size_t)NN * ED];
__device__ float    g_bioT[(size_t)ED * ED];
__device__ unsigned g_mask[(size_t)NN * MASKW];
__device__ float    g_rowent[NN];

// ---------------------------------------------------------------------------
// Helpers
// ---------------------------------------------------------------------------
__device__ __forceinline__ float warp_red_sum(float v) {
#pragma unroll
    for (int o = 16; o; o >>= 1) v += __shfl_xor_sync(0xffffffffu, v, o);
    return v;
}
__device__ __forceinline__ float warp_red_max(float v) {
#pragma unroll
    for (int o = 16; o; o >>= 1) v = fmaxf(v, __shfl_xor_sync(0xffffffffu, v, o));
    return v;
}
__device__ __forceinline__ float red16_max(float v) {
    v = fmaxf(v, __shfl_xor_sync(0xffffffffu, v, 8));
    v = fmaxf(v, __shfl_xor_sync(0xffffffffu, v, 4));
    v = fmaxf(v, __shfl_xor_sync(0xffffffffu, v, 2));
    v = fmaxf(v, __shfl_xor_sync(0xffffffffu, v, 1));
    return v;
}
__device__ __forceinline__ float red16_sum(float v) {
    v += __shfl_xor_sync(0xffffffffu, v, 8);
    v += __shfl_xor_sync(0xffffffffu, v, 4);
    v += __shfl_xor_sync(0xffffffffu, v, 2);
    v += __shfl_xor_sync(0xffffffffu, v, 1);
    return v;
}

__device__ __forceinline__ uint32_t f2tf32(float x) {
    uint32_t u;
    asm("cvt.rna.tf32.f32 %0, %1;" : "=r"(u) : "f"(x));
    return u;
}

__device__ __forceinline__ void mma8(float* c, const uint32_t* a, const uint32_t* b) {
    asm volatile(
        "mma.sync.aligned.m16n8k8.row.col.f32.tf32.tf32.f32 "
        "{%0,%1,%2,%3}, {%4,%5,%6,%7}, {%8,%9}, {%0,%1,%2,%3};"
        : "+f"(c[0]), "+f"(c[1]), "+f"(c[2]), "+f"(c[3])
        : "r"(a[0]), "r"(a[1]), "r"(a[2]), "r"(a[3]), "r"(b[0]), "r"(b[1]));
}

// ---------------------------------------------------------------------------
// Mask build
// ---------------------------------------------------------------------------
__global__ void zero_mask_kernel(unsigned* __restrict__ m) {
    m[(size_t)blockIdx.x * 1024 + threadIdx.x] = 0u;
}

__global__ void build_mask_kernel(const int* __restrict__ ei, int ne,
                                  unsigned* __restrict__ m) {
    int idx = blockIdx.x * blockDim.x + threadIdx.x;
    if (idx < ne) {
        int r = ei[idx];
        int c = ei[ne + idx];
        atomicOr(&m[(size_t)r * MASKW + (c >> 5)], 1u << (c & 31));
    }
}

// ---------------------------------------------------------------------------
// 512x512 transpose (bio -> bioT)
// ---------------------------------------------------------------------------
__global__ void transpose512_kernel(const float* __restrict__ in, float* __restrict__ out) {
    __shared__ float tile[32][33];
    int bx = blockIdx.x * 32, by = blockIdx.y * 32;
    int tx = threadIdx.x, ty = threadIdx.y;
#pragma unroll
    for (int j = 0; j < 32; j += 8)
        tile[ty + j][tx] = in[(size_t)(by + ty + j) * ED + bx + tx];
    __syncthreads();
#pragma unroll
    for (int j = 0; j < 32; j += 8)
        out[(size_t)(bx + ty + j) * ED + by + tx] = tile[tx][ty + j];
}

// ---------------------------------------------------------------------------
// fp32 SGEMM (NT), exact: C[M,N] = A[M,K] * B[N,K]^T  (+ epilogue)
// Used ONLY for the Q/K chain feeding atan2-phase (zero precision budget).
// 128x128 block tile, BK=16, 256 threads, 8x8 microtile.
// ---------------------------------------------------------------------------
#define BM 128
#define BN 128
#define BK 16

enum { EPI_BIAS = 0, EPI_CE = 1, EPI_MASK = 2 };

template <int EPI>
__global__ void __launch_bounds__(256)
sgemm_nt(const float* __restrict__ A,
         const float* __restrict__ B,
         float* __restrict__ C,
         int M, int N, int K,
         const float* __restrict__ bias,
         const int* __restrict__ ct,
         const float* __restrict__ cemb)
{
    __shared__ float As[BK][BM];
    __shared__ float Bs[BK][BN];

    const int tid = threadIdx.x;
    const int tx = tid & 15, ty = tid >> 4;
    const int bm = blockIdx.y * BM, bn = blockIdx.x * BN;

    const int lrow = tid >> 2;       // 0..63
    const int lc4  = (tid & 3) * 4;  // 0,4,8,12

    float acc[8][8];
#pragma unroll
    for (int i = 0; i < 8; ++i)
#pragma unroll
        for (int j = 0; j < 8; ++j) acc[i][j] = 0.f;

    for (int k0 = 0; k0 < K; k0 += BK) {
#pragma unroll
        for (int t = 0; t < 2; ++t) {
            int row = lrow + t * 64;
            float4 va = *(const float4*)(A + (size_t)(bm + row) * K + k0 + lc4);
            As[lc4 + 0][row] = va.x; As[lc4 + 1][row] = va.y;
            As[lc4 + 2][row] = va.z; As[lc4 + 3][row] = va.w;
            float4 vb = *(const float4*)(B + (size_t)(bn + row) * K + k0 + lc4);
            Bs[lc4 + 0][row] = vb.x; Bs[lc4 + 1][row] = vb.y;
            Bs[lc4 + 2][row] = vb.z; Bs[lc4 + 3][row] = vb.w;
        }
        __syncthreads();
#pragma unroll
        for (int kk = 0; kk < BK; ++kk) {
            float4 a0 = *(const float4*)&As[kk][ty * 8];
            float4 a1 = *(const float4*)&As[kk][ty * 8 + 4];
            float4 b0 = *(const float4*)&Bs[kk][tx * 8];
            float4 b1 = *(const float4*)&Bs[kk][tx * 8 + 4];
            float av[8] = {a0.x, a0.y, a0.z, a0.w, a1.x, a1.y, a1.z, a1.w};
            float bv[8] = {b0.x, b0.y, b0.z, b0.w, b1.x, b1.y, b1.z, b1.w};
#pragma unroll
            for (int i = 0; i < 8; ++i)
#pragma unroll
                for (int j = 0; j < 8; ++j)
                    acc[i][j] += av[i] * bv[j];
        }
        __syncthreads();
    }

#pragma unroll
    for (int i = 0; i < 8; ++i) {
        int gm = bm + ty * 8 + i;
#pragma unroll
        for (int j = 0; j < 8; ++j) {
            int gn = bn + tx * 8 + j;
            float v = acc[i][j];
            if (EPI == EPI_BIAS) {
                v += bias[gn];
            } else {
                v += 0.1f * cemb[(size_t)ct[gm] * N + gn];
            }
            C[(size_t)gm * N + gn] = v;
        }
    }
}

// ---------------------------------------------------------------------------
// tf32 tensor-core GEMM (NT):  C[M,N] = A[M,K] * B[N,K]^T  (+ epilogue)
// SPLIT=true: 3xTF32 (near-fp32), single-buffer smem + register prefetch.
// SPLIT=false: single tf32, double-buffered smem.
// 256 threads, 8 warps (4 in M x 2 in N), mma.sync.m16n8k8, smem pad 8.
// ---------------------------------------------------------------------------
template <int TBM, int TBN, int EPI, bool SPLIT>
__global__ void __launch_bounds__(256)
gemm_tf32(const float* __restrict__ A, long long sAz,
          const float* __restrict__ B, long long sBz,
          float* __restrict__ C, long long sCz,
          int M, int N, int K,
          const float* __restrict__ bias, long long sbz,
          const int* __restrict__ ct,
          const float* __restrict__ cemb,
          const unsigned* __restrict__ mask,
          float scale)
{
    constexpr int LDA = TBM + 8;
    constexpr int LDB = TBN + 8;
    constexpr int AF4 = (TBM * 16) / (4 * 256);
    constexpr int BF4 = (TBN * 16) / (4 * 256);
    constexpr int WM = TBM / 4, WN = TBN / 2;
    constexpr int MF = WM / 16, NF = WN / 8;
    constexpr int NC = SPLIT ? 2 : 1;
    constexpr int NBUF = SPLIT ? 1 : 2;

    __shared__ uint32_t As[NBUF][NC][16][LDA];
    __shared__ uint32_t Bs[NBUF][NC][16][LDB];

    A += (size_t)blockIdx.z * sAz;
    B += (size_t)blockIdx.z * sBz;
    C += (size_t)blockIdx.z * sCz;
    if (bias) bias += (size_t)blockIdx.z * sbz;

    const int tid = threadIdx.x;
    const int lane = tid & 31, wid = tid >> 5;
    const int wm = wid & 3, wn = wid >> 2;
    const int bm = blockIdx.y * TBM, bn = blockIdx.x * TBN;
    const int lq = lane >> 2, lr = lane & 3;

    float c[MF][NF][4];
#pragma unroll
    for (int i = 0; i < MF; ++i)
#pragma unroll
        for (int j = 0; j < NF; ++j)
#pragma unroll
            for (int r = 0; r < 4; ++r) c[i][j][r] = 0.f;

    float4 pa[AF4], pb[BF4];

    auto store_a = [&](int st) {
#pragma unroll
        for (int t = 0; t < AF4; ++t) {
            int f = tid + t * 256, m = f >> 2, k4 = (f & 3) * 4;
            float xs[4] = {pa[t].x, pa[t].y, pa[t].z, pa[t].w};
#pragma unroll
            for (int e = 0; e < 4; ++e) {
                uint32_t h = f2tf32(xs[e]);
                As[st][0][k4 + e][m] = h;
                if (SPLIT)
                    As[st][1][k4 + e][m] = f2tf32(xs[e] - __uint_as_float(h));
            }
        }
    };
    auto store_b = [&](int st) {
#pragma unroll
        for (int t = 0; t < BF4; ++t) {
            int f = tid + t * 256, n = f >> 2, k4 = (f & 3) * 4;
            float xs[4] = {pb[t].x, pb[t].y, pb[t].z, pb[t].w};
#pragma unroll
            for (int e = 0; e < 4; ++e) {
                uint32_t h = f2tf32(xs[e]);
                Bs[st][0][k4 + e][n] = h;
                if (SPLIT)
                    Bs[st][1][k4 + e][n] = f2tf32(xs[e] - __uint_as_float(h));
            }
        }
    };
    auto load_ab = [&](int k0) {
#pragma unroll
        for (int t = 0; t < AF4; ++t) {
            int f = tid + t * 256;
            pa[t] = *(const float4*)(A + (size_t)(bm + (f >> 2)) * K + k0 + (f & 3) * 4);
        }
#pragma unroll
        for (int t = 0; t < BF4; ++t) {
            int f = tid + t * 256;
            pb[t] = *(const float4*)(B + (size_t)(bn + (f >> 2)) * K + k0 + (f & 3) * 4);
        }
    };
    auto compute = [&](int st) {
#pragma unroll
        for (int ks = 0; ks < 16; ks += 8) {
            uint32_t af[MF][NC][4], bf[NF][NC][2];
#pragma unroll
            for (int i = 0; i < MF; ++i) {
                int m0 = wm * WM + i * 16;
#pragma unroll
                for (int cc = 0; cc < NC; ++cc) {
                    af[i][cc][0] = As[st][cc][ks + lr][m0 + lq];
                    af[i][cc][1] = As[st][cc][ks + lr][m0 + lq + 8];
                    af[i][cc][2] = As[st][cc][ks + lr + 4][m0 + lq];
                    af[i][cc][3] = As[st][cc][ks + lr + 4][m0 + lq + 8];
                }
            }
#pragma unroll
            for (int j = 0; j < NF; ++j) {
                int n0 = wn * WN + j * 8;
#pragma unroll
                for (int cc = 0; cc < NC; ++cc) {
                    bf[j][cc][0] = Bs[st][cc][ks + lr][n0 + lq];
                    bf[j][cc][1] = Bs[st][cc][ks + lr + 4][n0 + lq];
                }
            }
#pragma unroll
            for (int i = 0; i < MF; ++i)
#pragma unroll
                for (int j = 0; j < NF; ++j) {
                    mma8(c[i][j], af[i][0], bf[j][0]);
                    if (SPLIT) {
                        mma8(c[i][j], af[i][0], bf[j][1]);
                        mma8(c[i][j], af[i][1], bf[j][0]);
                    }
                }
        }
    };

    const int nk = K >> 4;

    if (!SPLIT) {
        load_ab(0);
        store_a(0); store_b(0);
        __syncthreads();
        int st = 0;
        for (int kt = 0; kt < nk; ++kt) {
            if (kt + 1 < nk) load_ab((kt + 1) << 4);
            compute(st);
            if (kt + 1 < nk) { store_a(st ^ 1); store_b(st ^ 1); }
            __syncthreads();
            st ^= 1;
        }
    } else {
        load_ab(0);
        store_a(0); store_b(0);
        __syncthreads();
        for (int kt = 0; kt < nk; ++kt) {
            if (kt + 1 < nk) load_ab((kt + 1) << 4);
            compute(0);
            __syncthreads();
            if (kt + 1 < nk) {
                store_a(0); store_b(0);
                __syncthreads();
            }
        }
    }

#pragma unroll
    for (int i = 0; i < MF; ++i) {
        int gm = bm + wm * WM + i * 16 + lq;
        int t0 = 0, t1 = 0;
        if (EPI == EPI_CE) { t0 = ct[gm]; t1 = ct[gm + 8]; }
#pragma unroll
        for (int j = 0; j < NF; ++j) {
            int gn = bn + wn * WN + j * 8 + lr * 2;
            float v00 = c[i][j][0], v01 = c[i][j][1];
            float v10 = c[i][j][2], v11 = c[i][j][3];
            if (EPI == EPI_BIAS) {
                float b0 = bias[gn], b1 = bias[gn + 1];
                v00 += b0; v01 += b1; v10 += b0; v11 += b1;
            } else if (EPI == EPI_CE) {
                v00 += 0.1f * cemb[(size_t)t0 * N + gn];
                v01 += 0.1f * cemb[(size_t)t0 * N + gn + 1];
                v10 += 0.1f * cemb[(size_t)t1 * N + gn];
                v11 += 0.1f * cemb[(size_t)t1 * N + gn + 1];
            } else {
                unsigned w0 = mask[(size_t)gm * MASKW + (gn >> 5)];
                unsigned w1 = mask[(size_t)(gm + 8) * MASKW + (gn >> 5)];
                v00 = ((w0 >> (gn & 31)) & 1u) ? v00 * scale : -1e9f;
                v01 = ((w0 >> ((gn + 1) & 31)) & 1u) ? v01 * scale : -1e9f;
                v10 = ((w1 >> (gn & 31)) & 1u) ? v10 * scale : -1e9f;
                v11 = ((w1 >> ((gn + 1) & 31)) & 1u) ? v11 * scale : -1e9f;
            }
            float2 r0 = {v00, v01}, r1 = {v10, v11};
            *(float2*)(C + (size_t)gm * N + gn) = r0;
            *(float2*)(C + (size_t)(gm + 8) * N + gn) = r1;
        }
    }
}

// ---------------------------------------------------------------------------
// phase = atan2(K, Q) elementwise
// ---------------------------------------------------------------------------
__global__ void phase_kernel(const float* __restrict__ Q, const float* __restrict__ K,
                             float* __restrict__ phase) {
    size_t i = (size_t)blockIdx.x * blockDim.x + threadIdx.x;
    phase[i] = atan2f(K[i], Q[i]);
}

// ---------------------------------------------------------------------------
// Row softmax over masked scores (in-place on attn region) + per-row entropy
// ---------------------------------------------------------------------------
__global__ void __launch_bounds__(256)
softmax_row_kernel(float* __restrict__ attn, float* __restrict__ row_ent) {
    __shared__ float red[8];
    __shared__ float bval;
    const int tid = threadIdx.x;
    const int wid = tid >> 5, lane = tid & 31;
    float* p = attn + (size_t)blockIdx.x * NN;

    float4 x[4];
#pragma unroll
    for (int t = 0; t < 4; ++t)
        x[t] = *(const float4*)(p + t * 1024 + tid * 4);

    float mx = NEG_INF;
#pragma unroll
    for (int t = 0; t < 4; ++t)
        mx = fmaxf(fmaxf(fmaxf(mx, x[t].x), fmaxf(x[t].y, x[t].z)), x[t].w);
    mx = warp_red_max(mx);
    if (lane == 0) red[wid] = mx;
    __syncthreads();
    if (wid == 0) {
        float v = (lane < 8) ? red[lane] : NEG_INF;
        v = warp_red_max(v);
        if (lane == 0) bval = v;
    }
    __syncthreads();
    mx = bval;
    __syncthreads();

    float e[16];
    float s = 0.f;
#pragma unroll
    for (int t = 0; t < 4; ++t) {
        e[t * 4 + 0] = __expf(x[t].x - mx);
        e[t * 4 + 1] = __expf(x[t].y - mx);
        e[t * 4 + 2] = __expf(x[t].z - mx);
        e[t * 4 + 3] = __expf(x[t].w - mx);
        s += e[t * 4 + 0] + e[t * 4 + 1] + e[t * 4 + 2] + e[t * 4 + 3];
    }
    s = warp_red_sum(s);
    if (lane == 0) red[wid] = s;
    __syncthreads();
    if (wid == 0) {
        float v = (lane < 8) ? red[lane] : 0.f;
        v = warp_red_sum(v);
        if (lane == 0) bval = v;
    }
    __syncthreads();
    const float inv = 1.0f / bval;
    __syncthreads();

    float ent = 0.f;
#pragma unroll
    for (int t = 0; t < 4; ++t) {
        float4 r;
        r.x = e[t * 4 + 0] * inv;
        r.y = e[t * 4 + 1] * inv;
        r.z = e[t * 4 + 2] * inv;
        r.w = e[t * 4 + 3] * inv;
        ent += r.x * logf(r.x + 1e-10f) + r.y * logf(r.y + 1e-10f)
             + r.z * logf(r.z + 1e-10f) + r.w * logf(r.w + 1e-10f);
        *(float4*)(p + t * 1024 + tid * 4) = r;
    }
    ent = warp_red_sum(ent);
    if (lane == 0) red[wid] = ent;
    __syncthreads();
    if (wid == 0) {
        float v = (lane < 8) ? red[lane] : 0.f;
        v = warp_red_sum(v);
        if (lane == 0) row_ent[blockIdx.x] = v;
    }
}

__global__ void reduce_entropy_kernel(const float* __restrict__ row_ent,
                                      float* __restrict__ coh) {
    __shared__ float red[32];
    int tid = threadIdx.x, lane = tid & 31, wid = tid >> 5;
    float v = row_ent[tid] + row_ent[tid + 1024] + row_ent[tid + 2048] + row_ent[tid + 3072];
    v = warp_red_sum(v);
    if (lane == 0) red[wid] = v;
    __syncthreads();
    if (wid == 0) {
        float s = red[lane];
        s = warp_red_sum(s);
        if (lane == 0) {
            float entropy = -s;
            *coh = 1.0f - entropy / logf((float)NN);
        }
    }
}

// ---------------------------------------------------------------------------
// Flash-style MHA (fp32): softmax(q k^T / 8) v, per head.
// ---------------------------------------------------------------------------
#define QS_LD 132
#define KS_LD 68

__global__ void __launch_bounds__(256, 2)
flash_mha(const float* __restrict__ q, const float* __restrict__ k,
          const float* __restrict__ v, float* __restrict__ o)
{
    extern __shared__ float sm[];
    float* qs = sm;                         // [64][132]  qs[d][m]
    float* ks = qs + 64 * QS_LD;            // [64][68]   ks[d][j]
    float* vs = ks + 64 * KS_LD;            // [64][68]   vs[j][dv]
    float* ps = vs + 64 * KS_LD;            // [64][132]  ps[j][m]

    const int tid = threadIdx.x;
    const int tx = tid & 15, ty = tid >> 4;
    const int head = blockIdx.y;
    const int qbase = blockIdx.x * 128;
    const int hoff = head * HD;
    const int m0 = ty * 8;

#pragma unroll
    for (int t = 0; t < 8; ++t) {
        int f = tid + t * 256;
        int row = f >> 4, c4 = (f & 15) * 4;
        float4 val = *(const float4*)(q + (size_t)(qbase + row) * ED + hoff + c4);
        qs[(c4 + 0) * QS_LD + row] = val.x;
        qs[(c4 + 1) * QS_LD + row] = val.y;
        qs[(c4 + 2) * QS_LD + row] = val.z;
        qs[(c4 + 3) * QS_LD + row] = val.w;
    }

    float m_i[8], l_i[8], oacc[8][4];
#pragma unroll
    for (int i = 0; i < 8; ++i) {
        m_i[i] = NEG_INF;
        l_i[i] = 0.f;
#pragma unroll
        for (int c = 0; c < 4; ++c) oacc[i][c] = 0.f;
    }

    for (int kt = 0; kt < NN / 64; ++kt) {
        __syncthreads();
#pragma unroll
        for (int t = 0; t < 4; ++t) {
            int f = tid + t * 256;
            int row = f >> 4, c4 = (f & 15) * 4;
            float4 kv = *(const float4*)(k + (size_t)(kt * 64 + row) * ED + hoff + c4);
            ks[(c4 + 0) * KS_LD + row] = kv.x;
            ks[(c4 + 1) * KS_LD + row] = kv.y;
            ks[(c4 + 2) * KS_LD + row] = kv.z;
            ks[(c4 + 3) * KS_LD + row] = kv.w;
            float4 vv = *(const float4*)(v + (size_t)(kt * 64 + row) * ED + hoff + c4);
            *(float4*)(vs + row * KS_LD + c4) = vv;
        }
        __syncthreads();

        float s[8][4];
#pragma unroll
        for (int i = 0; i < 8; ++i)
#pragma unroll
            for (int c = 0; c < 4; ++c) s[i][c] = 0.f;

#pragma unroll 4
        for (int d = 0; d < HD; ++d) {
            float4 b = *(const float4*)(ks + d * KS_LD + tx * 4);
            float4 a0 = *(const float4*)(qs + d * QS_LD + m0);
            float4 a1 = *(const float4*)(qs + d * QS_LD + m0 + 4);
            float av[8] = {a0.x, a0.y, a0.z, a0.w, a1.x, a1.y, a1.z, a1.w};
            float bv[4] = {b.x, b.y, b.z, b.w};
#pragma unroll
            for (int i = 0; i < 8; ++i)
#pragma unroll
                for (int c = 0; c < 4; ++c)
                    s[i][c] += av[i] * bv[c];
        }

#pragma unroll
        for (int i = 0; i < 8; ++i) {
#pragma unroll
            for (int c = 0; c < 4; ++c) s[i][c] *= 0.125f;
            float mx = fmaxf(fmaxf(s[i][0], s[i][1]), fmaxf(s[i][2], s[i][3]));
            mx = red16_max(mx);
            float mnew = fmaxf(m_i[i], mx);
            float corr = __expf(m_i[i] - mnew);
            m_i[i] = mnew;
            float p0 = __expf(s[i][0] - mnew);
            float p1 = __expf(s[i][1] - mnew);
            float p2 = __expf(s[i][2] - mnew);
            float p3 = __expf(s[i][3] - mnew);
            float ls = red16_sum(p0 + p1 + p2 + p3);
            l_i[i] = l_i[i] * corr + ls;
#pragma unroll
            for (int c = 0; c < 4; ++c) oacc[i][c] *= corr;
            ps[(tx * 4 + 0) * QS_LD + m0 + i] = p0;
            ps[(tx * 4 + 1) * QS_LD + m0 + i] = p1;
            ps[(tx * 4 + 2) * QS_LD + m0 + i] = p2;
            ps[(tx * 4 + 3) * QS_LD + m0 + i] = p3;
        }
        __syncwarp();

#pragma unroll 4
        for (int j = 0; j < 64; ++j) {
            float4 b = *(const float4*)(vs + j * KS_LD + tx * 4);
            float4 a0 = *(const float4*)(ps + j * QS_LD + m0);
            float4 a1 = *(const float4*)(ps + j * QS_LD + m0 + 4);
            float av[8] = {a0.x, a0.y, a0.z, a0.w, a1.x, a1.y, a1.z, a1.w};
            float bv[4] = {b.x, b.y, b.z, b.w};
#pragma unroll
            for (int i = 0; i < 8; ++i)
#pragma unroll
                for (int c = 0; c < 4; ++c)
                    oacc[i][c] += av[i] * bv[c];
        }
        __syncwarp();
    }

#pragma unroll
    for (int i = 0; i < 8; ++i) {
        float inv = 1.0f / l_i[i];
        float4 r;
        r.x = oacc[i][0] * inv;
        r.y = oacc[i][1] * inv;
        r.z = oacc[i][2] * inv;
        r.w = oacc[i][3] * inv;
        *(float4*)(o + (size_t)(qbase + m0 + i) * ED + hoff + tx * 4) = r;
    }
}

// ---------------------------------------------------------------------------
// Host launcher
// ---------------------------------------------------------------------------
extern "C" void kernel_launch(void* const* d_in, const int* in_sizes, int n_in,
                              void* d_out, int out_size)
{
    const float* nf   = (const float*)d_in[0];
    const int*   ei   = (const int*)  d_in[1];
    const int*   ct   = (const int*)  d_in[2];
    const float* Wq   = (const float*)d_in[3];
    const float* bq   = (const float*)d_in[4];
    const float* Wk   = (const float*)d_in[5];
    const float* bk   = (const float*)d_in[6];
    const float* Wv   = (const float*)d_in[7];
    const float* bv   = (const float*)d_in[8];
    const float* bio  = (const float*)d_in[9];
    const float* cemb = (const float*)d_in[10];
    const float* ipw  = (const float*)d_in[11];
    const float* ipb  = (const float*)d_in[12];
    const float* outw = (const float*)d_in[13];
    const float* outb = (const float*)d_in[14];

    float* out      = (float*)d_out;
    float* attended = out;                                    // [4096,512]
    float* attn     = out + (size_t)NN * ED;                  // [4096,4096]
    float* phase    = attn + (size_t)NN * NN;                 // [4096,512]
    float* coh      = phase + (size_t)NN * ED;                // scalar

    const int ne = in_sizes[1] / 2;
    const size_t NS = (size_t)NN * ED;

    float *Q0, *K0, *QKV, *qkv2, *og, *bioT, *rowent;
    unsigned* msk;
    cudaGetSymbolAddress((void**)&Q0,     g_Q0);
    cudaGetSymbolAddress((void**)&K0,     g_K0);
    cudaGetSymbolAddress((void**)&QKV,    g_QKV);
    cudaGetSymbolAddress((void**)&qkv2,   g_qkv2);
    cudaGetSymbolAddress((void**)&og,     g_o);
    cudaGetSymbolAddress((void**)&bioT,   g_bioT);
    cudaGetSymbolAddress((void**)&msk,    g_mask);
    cudaGetSymbolAddress((void**)&rowent, g_rowent);

    // edge mask
    zero_mask_kernel<<<(NN * MASKW) / 1024, 1024>>>(msk);
    build_mask_kernel<<<(ne + 255) / 256, 256>>>(ei, ne, msk);

    // bio^T for Q-side mixing
    transpose512_kernel<<<dim3(16, 16), dim3(32, 8)>>>(bio, bioT);

    // ---- Q/K chain feeding phase: EXACT fp32 (FFMA) ----
    sgemm_nt<EPI_BIAS><<<dim3(4, 32), 256>>>(nf, Wq, Q0, NN, ED, DIN, bq, nullptr, nullptr);
    sgemm_nt<EPI_BIAS><<<dim3(4, 32), 256>>>(nf, Wk, K0, NN, ED, DIN, bk, nullptr, nullptr);
    sgemm_nt<EPI_CE><<<dim3(4, 32), 256>>>(Q0, bioT, QKV, NN, ED, ED, nullptr, ct, cemb);
    sgemm_nt<EPI_CE><<<dim3(4, 32), 256>>>(K0, bio, QKV + NS, NN, ED, ED, nullptr, ct, cemb);

    // V projection (3xTF32, feeds only attended)
    gemm_tf32<64, 128, EPI_BIAS, true><<<dim3(4, 64), 256>>>(nf, 0, Wv, 0, QKV + 2 * NS, 0,
                                                             NN, ED, DIN,
                                                             bv, 0, nullptr, nullptr, nullptr, 0.f);

    // phase = atan2(Kf, Qf)  (exact inputs)
    phase_kernel<<<(NN * ED) / 1024, 1024>>>(QKV, QKV + NS, phase);

    // masked scores -> attn region (1xTF32):  Qf @ Kf^T / sqrt(512), -1e9 off-edge
    gemm_tf32<128, 128, EPI_MASK, false><<<dim3(32, 32), 256>>>(QKV, 0, QKV + NS, 0, attn, 0,
                                                                NN, NN, ED,
                                                                nullptr, 0, nullptr, nullptr, msk,
                                                                0.044194173824159216f);

    // row softmax in-place + per-row entropy, then coherence
    softmax_row_kernel<<<NN, 256>>>(attn, rowent);
    reduce_entropy_kernel<<<1, 1024>>>(rowent, coh);

    // in_proj (3xTF32, batched z=3): q/k/v = {Qf,Kf,V} @ ipw[z]^T + ipb[z]
    gemm_tf32<64, 128, EPI_BIAS, true><<<dim3(4, 64, 3), 256>>>(QKV, (long long)NS,
                                                                ipw, (long long)ED * ED,
                                                                qkv2, (long long)NS,
                                                                NN, ED, ED,
                                                                ipb, (long long)ED,
                                                                nullptr, nullptr, nullptr, 0.f);

    // flash MHA per head (fp32)
    cudaFuncSetAttribute(flash_mha, cudaFuncAttributeMaxDynamicSharedMemorySize, 102400);
    flash_mha<<<dim3(NN / 128, NHEAD), 256, 102400>>>(qkv2, qkv2 + NS, qkv2 + 2 * NS, og);

    // output projection (3xTF32)
    gemm_tf32<64, 128, EPI_BIAS, true><<<dim3(4, 64), 256>>>(og, 0, outw, 0, attended, 0,
                                                             NN, ED, ED,
                                                             outb, 0, nullptr, nullptr, nullptr, 0.f);
}

// round 8
// speedup vs baseline: 1.8167x; 1.5845x over previous
#include <cuda_runtime.h>
#include <math.h>
#include <stdint.h>

// ---------------------------------------------------------------------------
// Problem constants
// ---------------------------------------------------------------------------
#define NN 4096          // nodes
#define DIN 256          // input dim
#define ED 512           // quantum dim
#define NHEAD 8
#define HD 64
#define MASKW 128        // 4096/32 words per row

#define NEG_INF (__int_as_float(0xff800000))

// ---------------------------------------------------------------------------
// Scratch (device globals; no allocation allowed)
// ---------------------------------------------------------------------------
__device__ float    g_Q0[(size_t)NN * ED];
__device__ float    g_K0[(size_t)NN * ED];
__device__ float    g_QKV[(size_t)3 * NN * ED];   // Qfinal, Kfinal, V
__device__ float    g_qkv2[(size_t)3 * NN * ED];  // q, k, v after in_proj
__device__ float    g_o[(size_t)NN * ED];
__device__ float    g_bioT[(size_t)ED * ED];
__device__ unsigned g_mask[(size_t)NN * MASKW];
__device__ float    g_rowent[NN];

// ---------------------------------------------------------------------------
// Helpers
// ---------------------------------------------------------------------------
__device__ __forceinline__ float warp_red_sum(float v) {
#pragma unroll
    for (int o = 16; o; o >>= 1) v += __shfl_xor_sync(0xffffffffu, v, o);
    return v;
}
__device__ __forceinline__ float warp_red_max(float v) {
#pragma unroll
    for (int o = 16; o; o >>= 1) v = fmaxf(v, __shfl_xor_sync(0xffffffffu, v, o));
    return v;
}

__device__ __forceinline__ uint32_t f2tf32(float x) {
    uint32_t u;
    asm("cvt.rna.tf32.f32 %0, %1;" : "=r"(u) : "f"(x));
    return u;
}

__device__ __forceinline__ void mma8(float* c, const uint32_t* a, const uint32_t* b) {
    asm volatile(
        "mma.sync.aligned.m16n8k8.row.col.f32.tf32.tf32.f32 "
        "{%0,%1,%2,%3}, {%4,%5,%6,%7}, {%8,%9}, {%0,%1,%2,%3};"
        : "+f"(c[0]), "+f"(c[1]), "+f"(c[2]), "+f"(c[3])
        : "r"(a[0]), "r"(a[1]), "r"(a[2]), "r"(a[3]), "r"(b[0]), "r"(b[1]));
}

// ---------------------------------------------------------------------------
// Mask build
// ---------------------------------------------------------------------------
__global__ void zero_mask_kernel(unsigned* __restrict__ m) {
    m[(size_t)blockIdx.x * 1024 + threadIdx.x] = 0u;
}

__global__ void build_mask_kernel(const int* __restrict__ ei, int ne,
                                  unsigned* __restrict__ m) {
    int idx = blockIdx.x * blockDim.x + threadIdx.x;
    if (idx < ne) {
        int r = ei[idx];
        int c = ei[ne + idx];
        atomicOr(&m[(size_t)r * MASKW + (c >> 5)], 1u << (c & 31));
    }
}

// ---------------------------------------------------------------------------
// 512x512 transpose (bio -> bioT)
// ---------------------------------------------------------------------------
__global__ void transpose512_kernel(const float* __restrict__ in, float* __restrict__ out) {
    __shared__ float tile[32][33];
    int bx = blockIdx.x * 32, by = blockIdx.y * 32;
    int tx = threadIdx.x, ty = threadIdx.y;
#pragma unroll
    for (int j = 0; j < 32; j += 8)
        tile[ty + j][tx] = in[(size_t)(by + ty + j) * ED + bx + tx];
    __syncthreads();
#pragma unroll
    for (int j = 0; j < 32; j += 8)
        out[(size_t)(bx + ty + j) * ED + by + tx] = tile[tx][ty + j];
}

// ---------------------------------------------------------------------------
// fp32 SGEMM (NT), exact: C[M,N] = A[M,K] * B[N,K]^T  (+ epilogue)
// Used ONLY for the Q/K chain feeding atan2-phase (zero precision budget).
// ---------------------------------------------------------------------------
#define BM 128
#define BN 128
#define BK 16

enum { EPI_BIAS = 0, EPI_CE = 1, EPI_MASK = 2 };

template <int EPI>
__global__ void __launch_bounds__(256)
sgemm_nt(const float* __restrict__ A,
         const float* __restrict__ B,
         float* __restrict__ C,
         int M, int N, int K,
         const float* __restrict__ bias,
         const int* __restrict__ ct,
         const float* __restrict__ cemb)
{
    __shared__ float As[BK][BM];
    __shared__ float Bs[BK][BN];

    const int tid = threadIdx.x;
    const int tx = tid & 15, ty = tid >> 4;
    const int bm = blockIdx.y * BM, bn = blockIdx.x * BN;

    const int lrow = tid >> 2;
    const int lc4  = (tid & 3) * 4;

    float acc[8][8];
#pragma unroll
    for (int i = 0; i < 8; ++i)
#pragma unroll
        for (int j = 0; j < 8; ++j) acc[i][j] = 0.f;

    for (int k0 = 0; k0 < K; k0 += BK) {
#pragma unroll
        for (int t = 0; t < 2; ++t) {
            int row = lrow + t * 64;
            float4 va = *(const float4*)(A + (size_t)(bm + row) * K + k0 + lc4);
            As[lc4 + 0][row] = va.x; As[lc4 + 1][row] = va.y;
            As[lc4 + 2][row] = va.z; As[lc4 + 3][row] = va.w;
            float4 vb = *(const float4*)(B + (size_t)(bn + row) * K + k0 + lc4);
            Bs[lc4 + 0][row] = vb.x; Bs[lc4 + 1][row] = vb.y;
            Bs[lc4 + 2][row] = vb.z; Bs[lc4 + 3][row] = vb.w;
        }
        __syncthreads();
#pragma unroll
        for (int kk = 0; kk < BK; ++kk) {
            float4 a0 = *(const float4*)&As[kk][ty * 8];
            float4 a1 = *(const float4*)&As[kk][ty * 8 + 4];
            float4 b0 = *(const float4*)&Bs[kk][tx * 8];
            float4 b1 = *(const float4*)&Bs[kk][tx * 8 + 4];
            float av[8] = {a0.x, a0.y, a0.z, a0.w, a1.x, a1.y, a1.z, a1.w};
            float bv[8] = {b0.x, b0.y, b0.z, b0.w, b1.x, b1.y, b1.z, b1.w};
#pragma unroll
            for (int i = 0; i < 8; ++i)
#pragma unroll
                for (int j = 0; j < 8; ++j)
                    acc[i][j] += av[i] * bv[j];
        }
        __syncthreads();
    }

#pragma unroll
    for (int i = 0; i < 8; ++i) {
        int gm = bm + ty * 8 + i;
#pragma unroll
        for (int j = 0; j < 8; ++j) {
            int gn = bn + tx * 8 + j;
            float v = acc[i][j];
            if (EPI == EPI_BIAS) {
                v += bias[gn];
            } else {
                v += 0.1f * cemb[(size_t)ct[gm] * N + gn];
            }
            C[(size_t)gm * N + gn] = v;
        }
    }
}

// ---------------------------------------------------------------------------
// tf32 tensor-core GEMM (NT):  C[M,N] = A[M,K] * B[N,K]^T  (+ epilogue)
// SPLIT=true: 3xTF32 (near-fp32). SPLIT=false: single tf32, double-buffered.
// ---------------------------------------------------------------------------
template <int TBM, int TBN, int EPI, bool SPLIT>
__global__ void __launch_bounds__(256)
gemm_tf32(const float* __restrict__ A, long long sAz,
          const float* __restrict__ B, long long sBz,
          float* __restrict__ C, long long sCz,
          int M, int N, int K,
          const float* __restrict__ bias, long long sbz,
          const int* __restrict__ ct,
          const float* __restrict__ cemb,
          const unsigned* __restrict__ mask,
          float scale)
{
    constexpr int LDA = TBM + 8;
    constexpr int LDB = TBN + 8;
    constexpr int AF4 = (TBM * 16) / (4 * 256);
    constexpr int BF4 = (TBN * 16) / (4 * 256);
    constexpr int WM = TBM / 4, WN = TBN / 2;
    constexpr int MF = WM / 16, NF = WN / 8;
    constexpr int NC = SPLIT ? 2 : 1;
    constexpr int NBUF = SPLIT ? 1 : 2;

    __shared__ uint32_t As[NBUF][NC][16][LDA];
    __shared__ uint32_t Bs[NBUF][NC][16][LDB];

    A += (size_t)blockIdx.z * sAz;
    B += (size_t)blockIdx.z * sBz;
    C += (size_t)blockIdx.z * sCz;
    if (bias) bias += (size_t)blockIdx.z * sbz;

    const int tid = threadIdx.x;
    const int lane = tid & 31, wid = tid >> 5;
    const int wm = wid & 3, wn = wid >> 2;
    const int bm = blockIdx.y * TBM, bn = blockIdx.x * TBN;
    const int lq = lane >> 2, lr = lane & 3;

    float c[MF][NF][4];
#pragma unroll
    for (int i = 0; i < MF; ++i)
#pragma unroll
        for (int j = 0; j < NF; ++j)
#pragma unroll
            for (int r = 0; r < 4; ++r) c[i][j][r] = 0.f;

    float4 pa[AF4], pb[BF4];

    auto store_a = [&](int st) {
#pragma unroll
        for (int t = 0; t < AF4; ++t) {
            int f = tid + t * 256, m = f >> 2, k4 = (f & 3) * 4;
            float xs[4] = {pa[t].x, pa[t].y, pa[t].z, pa[t].w};
#pragma unroll
            for (int e = 0; e < 4; ++e) {
                uint32_t h = f2tf32(xs[e]);
                As[st][0][k4 + e][m] = h;
                if (SPLIT)
                    As[st][1][k4 + e][m] = f2tf32(xs[e] - __uint_as_float(h));
            }
        }
    };
    auto store_b = [&](int st) {
#pragma unroll
        for (int t = 0; t < BF4; ++t) {
            int f = tid + t * 256, n = f >> 2, k4 = (f & 3) * 4;
            float xs[4] = {pb[t].x, pb[t].y, pb[t].z, pb[t].w};
#pragma unroll
            for (int e = 0; e < 4; ++e) {
                uint32_t h = f2tf32(xs[e]);
                Bs[st][0][k4 + e][n] = h;
                if (SPLIT)
                    Bs[st][1][k4 + e][n] = f2tf32(xs[e] - __uint_as_float(h));
            }
        }
    };
    auto load_ab = [&](int k0) {
#pragma unroll
        for (int t = 0; t < AF4; ++t) {
            int f = tid + t * 256;
            pa[t] = *(const float4*)(A + (size_t)(bm + (f >> 2)) * K + k0 + (f & 3) * 4);
        }
#pragma unroll
        for (int t = 0; t < BF4; ++t) {
            int f = tid + t * 256;
            pb[t] = *(const float4*)(B + (size_t)(bn + (f >> 2)) * K + k0 + (f & 3) * 4);
        }
    };
    auto compute = [&](int st) {
#pragma unroll
        for (int ks = 0; ks < 16; ks += 8) {
            uint32_t af[MF][NC][4], bf[NF][NC][2];
#pragma unroll
            for (int i = 0; i < MF; ++i) {
                int m0 = wm * WM + i * 16;
#pragma unroll
                for (int cc = 0; cc < NC; ++cc) {
                    af[i][cc][0] = As[st][cc][ks + lr][m0 + lq];
                    af[i][cc][1] = As[st][cc][ks + lr][m0 + lq + 8];
                    af[i][cc][2] = As[st][cc][ks + lr + 4][m0 + lq];
                    af[i][cc][3] = As[st][cc][ks + lr + 4][m0 + lq + 8];
                }
            }
#pragma unroll
            for (int j = 0; j < NF; ++j) {
                int n0 = wn * WN + j * 8;
#pragma unroll
                for (int cc = 0; cc < NC; ++cc) {
                    bf[j][cc][0] = Bs[st][cc][ks + lr][n0 + lq];
                    bf[j][cc][1] = Bs[st][cc][ks + lr + 4][n0 + lq];
                }
            }
#pragma unroll
            for (int i = 0; i < MF; ++i)
#pragma unroll
                for (int j = 0; j < NF; ++j) {
                    mma8(c[i][j], af[i][0], bf[j][0]);
                    if (SPLIT) {
                        mma8(c[i][j], af[i][0], bf[j][1]);
                        mma8(c[i][j], af[i][1], bf[j][0]);
                    }
                }
        }
    };

    const int nk = K >> 4;

    if (!SPLIT) {
        load_ab(0);
        store_a(0); store_b(0);
        __syncthreads();
        int st = 0;
        for (int kt = 0; kt < nk; ++kt) {
            if (kt + 1 < nk) load_ab((kt + 1) << 4);
            compute(st);
            if (kt + 1 < nk) { store_a(st ^ 1); store_b(st ^ 1); }
            __syncthreads();
            st ^= 1;
        }
    } else {
        load_ab(0);
        store_a(0); store_b(0);
        __syncthreads();
        for (int kt = 0; kt < nk; ++kt) {
            if (kt + 1 < nk) load_ab((kt + 1) << 4);
            compute(0);
            __syncthreads();
            if (kt + 1 < nk) {
                store_a(0); store_b(0);
                __syncthreads();
            }
        }
    }

#pragma unroll
    for (int i = 0; i < MF; ++i) {
        int gm = bm + wm * WM + i * 16 + lq;
        int t0 = 0, t1 = 0;
        if (EPI == EPI_CE) { t0 = ct[gm]; t1 = ct[gm + 8]; }
#pragma unroll
        for (int j = 0; j < NF; ++j) {
            int gn = bn + wn * WN + j * 8 + lr * 2;
            float v00 = c[i][j][0], v01 = c[i][j][1];
            float v10 = c[i][j][2], v11 = c[i][j][3];
            if (EPI == EPI_BIAS) {
                float b0 = bias[gn], b1 = bias[gn + 1];
                v00 += b0; v01 += b1; v10 += b0; v11 += b1;
            } else if (EPI == EPI_CE) {
                v00 += 0.1f * cemb[(size_t)t0 * N + gn];
                v01 += 0.1f * cemb[(size_t)t0 * N + gn + 1];
                v10 += 0.1f * cemb[(size_t)t1 * N + gn];
                v11 += 0.1f * cemb[(size_t)t1 * N + gn + 1];
            } else {
                unsigned w0 = mask[(size_t)gm * MASKW + (gn >> 5)];
                unsigned w1 = mask[(size_t)(gm + 8) * MASKW + (gn >> 5)];
                v00 = ((w0 >> (gn & 31)) & 1u) ? v00 * scale : -1e9f;
                v01 = ((w0 >> ((gn + 1) & 31)) & 1u) ? v01 * scale : -1e9f;
                v10 = ((w1 >> (gn & 31)) & 1u) ? v10 * scale : -1e9f;
                v11 = ((w1 >> ((gn + 1) & 31)) & 1u) ? v11 * scale : -1e9f;
            }
            float2 r0 = {v00, v01}, r1 = {v10, v11};
            *(float2*)(C + (size_t)gm * N + gn) = r0;
            *(float2*)(C + (size_t)(gm + 8) * N + gn) = r1;
        }
    }
}

// ---------------------------------------------------------------------------
// phase = atan2(K, Q) elementwise
// ---------------------------------------------------------------------------
__global__ void phase_kernel(const float* __restrict__ Q, const float* __restrict__ K,
                             float* __restrict__ phase) {
    size_t i = (size_t)blockIdx.x * blockDim.x + threadIdx.x;
    phase[i] = atan2f(K[i], Q[i]);
}

// ---------------------------------------------------------------------------
// Row softmax over masked scores (in-place on attn region) + per-row entropy
// ---------------------------------------------------------------------------
__global__ void __launch_bounds__(256)
softmax_row_kernel(float* __restrict__ attn, float* __restrict__ row_ent) {
    __shared__ float red[8];
    __shared__ float bval;
    const int tid = threadIdx.x;
    const int wid = tid >> 5, lane = tid & 31;
    float* p = attn + (size_t)blockIdx.x * NN;

    float4 x[4];
#pragma unroll
    for (int t = 0; t < 4; ++t)
        x[t] = *(const float4*)(p + t * 1024 + tid * 4);

    float mx = NEG_INF;
#pragma unroll
    for (int t = 0; t < 4; ++t)
        mx = fmaxf(fmaxf(fmaxf(mx, x[t].x), fmaxf(x[t].y, x[t].z)), x[t].w);
    mx = warp_red_max(mx);
    if (lane == 0) red[wid] = mx;
    __syncthreads();
    if (wid == 0) {
        float v = (lane < 8) ? red[lane] : NEG_INF;
        v = warp_red_max(v);
        if (lane == 0) bval = v;
    }
    __syncthreads();
    mx = bval;
    __syncthreads();

    float e[16];
    float s = 0.f;
#pragma unroll
    for (int t = 0; t < 4; ++t) {
        e[t * 4 + 0] = __expf(x[t].x - mx);
        e[t * 4 + 1] = __expf(x[t].y - mx);
        e[t * 4 + 2] = __expf(x[t].z - mx);
        e[t * 4 + 3] = __expf(x[t].w - mx);
        s += e[t * 4 + 0] + e[t * 4 + 1] + e[t * 4 + 2] + e[t * 4 + 3];
    }
    s = warp_red_sum(s);
    if (lane == 0) red[wid] = s;
    __syncthreads();
    if (wid == 0) {
        float v = (lane < 8) ? red[lane] : 0.f;
        v = warp_red_sum(v);
        if (lane == 0) bval = v;
    }
    __syncthreads();
    const float inv = 1.0f / bval;
    __syncthreads();

    float ent = 0.f;
#pragma unroll
    for (int t = 0; t < 4; ++t) {
        float4 r;
        r.x = e[t * 4 + 0] * inv;
        r.y = e[t * 4 + 1] * inv;
        r.z = e[t * 4 + 2] * inv;
        r.w = e[t * 4 + 3] * inv;
        ent += r.x * logf(r.x + 1e-10f) + r.y * logf(r.y + 1e-10f)
             + r.z * logf(r.z + 1e-10f) + r.w * logf(r.w + 1e-10f);
        *(float4*)(p + t * 1024 + tid * 4) = r;
    }
    ent = warp_red_sum(ent);
    if (lane == 0) red[wid] = ent;
    __syncthreads();
    if (wid == 0) {
        float v = (lane < 8) ? red[lane] : 0.f;
        v = warp_red_sum(v);
        if (lane == 0) row_ent[blockIdx.x] = v;
    }
}

__global__ void reduce_entropy_kernel(const float* __restrict__ row_ent,
                                      float* __restrict__ coh) {
    __shared__ float red[32];
    int tid = threadIdx.x, lane = tid & 31, wid = tid >> 5;
    float v = row_ent[tid] + row_ent[tid + 1024] + row_ent[tid + 2048] + row_ent[tid + 3072];
    v = warp_red_sum(v);
    if (lane == 0) red[wid] = v;
    __syncthreads();
    if (wid == 0) {
        float s = red[lane];
        s = warp_red_sum(s);
        if (lane == 0) {
            float entropy = -s;
            *coh = 1.0f - entropy / logf((float)NN);
        }
    }
}

// ---------------------------------------------------------------------------
// Flash MHA on tf32 tensor cores: softmax(q k^T / 8) v, per head.
// Block = 128 q rows x 1 head, 8 warps (warp w owns rows 16w..16w+15, so all
// softmax row reductions are 2 shfl.xor within a lane quad).
// Q fragments register-resident (pre-scaled by exact 1/8). K/V double-buffered
// smem with register prefetch. P round-trips through smem in natural layout.
// Leading dims: %32==12 for lq-walked rows, %32==8 for lr-walked rows ->
// conflict-free fragment LDS.
// ---------------------------------------------------------------------------
#define QLD 76
#define PLD 76
#define KLD 76
#define VLD 72
#define KTS (64 * KLD)
#define VTS (64 * VLD)

__global__ void __launch_bounds__(256)
flash_mha_tf32(const float* __restrict__ q, const float* __restrict__ k,
               const float* __restrict__ v, float* __restrict__ o)
{
    extern __shared__ uint32_t sm[];
    uint32_t* Qn = sm;                    // [128][QLD]
    uint32_t* Pn = Qn + 128 * QLD;        // [128][PLD]
    uint32_t* Ks = Pn + 128 * PLD;        // [2][64][KLD]
    uint32_t* Vs = Ks + 2 * KTS;          // [2][64][VLD]

    const int tid = threadIdx.x;
    const int lane = tid & 31, wid = tid >> 5;
    const int lq = lane >> 2, lr = lane & 3;
    const int qbase = blockIdx.x * 128;
    const int hoff = blockIdx.y * HD;
    const int m0 = wid * 16;

    // Q -> smem natural [row][d], tf32, pre-scaled by 1/8 (exact power of 2)
#pragma unroll
    for (int t = 0; t < 8; ++t) {
        int f = tid + t * 256;                  // 0..2047 float4s
        int row = f >> 4, c4 = (f & 15) * 4;
        float4 val = *(const float4*)(q + (size_t)(qbase + row) * ED + hoff + c4);
        Qn[row * QLD + c4 + 0] = f2tf32(0.125f * val.x);
        Qn[row * QLD + c4 + 1] = f2tf32(0.125f * val.y);
        Qn[row * QLD + c4 + 2] = f2tf32(0.125f * val.z);
        Qn[row * QLD + c4 + 3] = f2tf32(0.125f * val.w);
    }
    __syncthreads();

    // Q fragments to registers: a0=[lq][lr], a1=[lq+8][lr], a2=[lq][lr+4], a3=[lq+8][lr+4]
    uint32_t qa[8][4];
#pragma unroll
    for (int ks = 0; ks < 8; ++ks) {
        qa[ks][0] = Qn[(m0 + lq) * QLD + ks * 8 + lr];
        qa[ks][1] = Qn[(m0 + lq + 8) * QLD + ks * 8 + lr];
        qa[ks][2] = Qn[(m0 + lq) * QLD + ks * 8 + lr + 4];
        qa[ks][3] = Qn[(m0 + lq + 8) * QLD + ks * 8 + lr + 4];
    }

    float m_i[2] = {NEG_INF, NEG_INF};
    float l_i[2] = {0.f, 0.f};
    float oacc[8][4];
#pragma unroll
    for (int j = 0; j < 8; ++j)
#pragma unroll
        for (int r = 0; r < 4; ++r) oacc[j][r] = 0.f;

    float4 kreg[4], vreg[4];
    auto ldgkv = [&](int kt) {
#pragma unroll
        for (int t = 0; t < 4; ++t) {
            int f = tid + t * 256;              // 0..1023 float4s
            int row = f >> 4, c4 = (f & 15) * 4;
            kreg[t] = *(const float4*)(k + (size_t)(kt * 64 + row) * ED + hoff + c4);
            vreg[t] = *(const float4*)(v + (size_t)(kt * 64 + row) * ED + hoff + c4);
        }
    };
    auto stkv = [&](int st) {
        uint32_t* kb = Ks + st * KTS;
        uint32_t* vb = Vs + st * VTS;
#pragma unroll
        for (int t = 0; t < 4; ++t) {
            int f = tid + t * 256;
            int row = f >> 4, c4 = (f & 15) * 4;
            kb[row * KLD + c4 + 0] = f2tf32(kreg[t].x);
            kb[row * KLD + c4 + 1] = f2tf32(kreg[t].y);
            kb[row * KLD + c4 + 2] = f2tf32(kreg[t].z);
            kb[row * KLD + c4 + 3] = f2tf32(kreg[t].w);
            vb[row * VLD + c4 + 0] = f2tf32(vreg[t].x);
            vb[row * VLD + c4 + 1] = f2tf32(vreg[t].y);
            vb[row * VLD + c4 + 2] = f2tf32(vreg[t].z);
            vb[row * VLD + c4 + 3] = f2tf32(vreg[t].w);
        }
    };

    ldgkv(0);
    stkv(0);
    __syncthreads();

    int st = 0;
    for (int kt = 0; kt < NN / 64; ++kt) {
        if (kt + 1 < NN / 64) ldgkv(kt + 1);

        const uint32_t* kb = Ks + st * KTS;
        const uint32_t* vb = Vs + st * VTS;

        // S = Q K^T (already scaled by 1/8 via Q)
        float s[8][4];
#pragma unroll
        for (int j = 0; j < 8; ++j)
#pragma unroll
            for (int r = 0; r < 4; ++r) s[j][r] = 0.f;

#pragma unroll
        for (int ks = 0; ks < 8; ++ks) {
            uint32_t bf[8][2];
#pragma unroll
            for (int j = 0; j < 8; ++j) {
                bf[j][0] = kb[(j * 8 + lq) * KLD + ks * 8 + lr];
                bf[j][1] = kb[(j * 8 + lq) * KLD + ks * 8 + lr + 4];
            }
#pragma unroll
            for (int j = 0; j < 8; ++j)
                mma8(s[j], qa[ks], bf[j]);
        }

        // online softmax; rows lq (r0,r1) and lq+8 (r2,r3)
        float mx0 = NEG_INF, mx1 = NEG_INF;
#pragma unroll
        for (int j = 0; j < 8; ++j) {
            mx0 = fmaxf(mx0, fmaxf(s[j][0], s[j][1]));
            mx1 = fmaxf(mx1, fmaxf(s[j][2], s[j][3]));
        }
        mx0 = fmaxf(mx0, __shfl_xor_sync(0xffffffffu, mx0, 1));
        mx0 = fmaxf(mx0, __shfl_xor_sync(0xffffffffu, mx0, 2));
        mx1 = fmaxf(mx1, __shfl_xor_sync(0xffffffffu, mx1, 1));
        mx1 = fmaxf(mx1, __shfl_xor_sync(0xffffffffu, mx1, 2));

        float mn0 = fmaxf(m_i[0], mx0), mn1 = fmaxf(m_i[1], mx1);
        float c0 = __expf(m_i[0] - mn0), c1 = __expf(m_i[1] - mn1);
        m_i[0] = mn0; m_i[1] = mn1;

        float ls0 = 0.f, ls1 = 0.f;
#pragma unroll
        for (int j = 0; j < 8; ++j) {
            float p0 = __expf(s[j][0] - mn0);
            float p1 = __expf(s[j][1] - mn0);
            float p2 = __expf(s[j][2] - mn1);
            float p3 = __expf(s[j][3] - mn1);
            ls0 += p0 + p1;
            ls1 += p2 + p3;
            Pn[(m0 + lq) * PLD + j * 8 + 2 * lr]     = f2tf32(p0);
            Pn[(m0 + lq) * PLD + j * 8 + 2 * lr + 1] = f2tf32(p1);
            Pn[(m0 + lq + 8) * PLD + j * 8 + 2 * lr]     = f2tf32(p2);
            Pn[(m0 + lq + 8) * PLD + j * 8 + 2 * lr + 1] = f2tf32(p3);
        }
        ls0 += __shfl_xor_sync(0xffffffffu, ls0, 1);
        ls0 += __shfl_xor_sync(0xffffffffu, ls0, 2);
        ls1 += __shfl_xor_sync(0xffffffffu, ls1, 1);
        ls1 += __shfl_xor_sync(0xffffffffu, ls1, 2);
        l_i[0] = l_i[0] * c0 + ls0;
        l_i[1] = l_i[1] * c1 + ls1;

#pragma unroll
        for (int j = 0; j < 8; ++j) {
            oacc[j][0] *= c0; oacc[j][1] *= c0;
            oacc[j][2] *= c1; oacc[j][3] *= c1;
        }
        __syncwarp();

        // O += P V
#pragma unroll
        for (int ks = 0; ks < 8; ++ks) {
            uint32_t pa4[4];
            pa4[0] = Pn[(m0 + lq) * PLD + ks * 8 + lr];
            pa4[1] = Pn[(m0 + lq + 8) * PLD + ks * 8 + lr];
            pa4[2] = Pn[(m0 + lq) * PLD + ks * 8 + lr + 4];
            pa4[3] = Pn[(m0 + lq + 8) * PLD + ks * 8 + lr + 4];
            uint32_t bf[8][2];
#pragma unroll
            for (int j = 0; j < 8; ++j) {
                bf[j][0] = vb[(ks * 8 + lr) * VLD + j * 8 + lq];
                bf[j][1] = vb[(ks * 8 + lr + 4) * VLD + j * 8 + lq];
            }
#pragma unroll
            for (int j = 0; j < 8; ++j)
                mma8(oacc[j], pa4, bf[j]);
        }
        __syncwarp();

        if (kt + 1 < NN / 64) stkv(st ^ 1);
        __syncthreads();
        st ^= 1;
    }

    // normalize + store (C-frag layout: rows lq/lq+8, cols j*8+2lr,+1)
    float inv0 = 1.0f / l_i[0], inv1 = 1.0f / l_i[1];
#pragma unroll
    for (int j = 0; j < 8; ++j) {
        float2 r0 = {oacc[j][0] * inv0, oacc[j][1] * inv0};
        float2 r1 = {oacc[j][2] * inv1, oacc[j][3] * inv1};
        *(float2*)(o + (size_t)(qbase + m0 + lq) * ED + hoff + j * 8 + 2 * lr) = r0;
        *(float2*)(o + (size_t)(qbase + m0 + lq + 8) * ED + hoff + j * 8 + 2 * lr) = r1;
    }
}

// ---------------------------------------------------------------------------
// Host launcher
// ---------------------------------------------------------------------------
extern "C" void kernel_launch(void* const* d_in, const int* in_sizes, int n_in,
                              void* d_out, int out_size)
{
    const float* nf   = (const float*)d_in[0];
    const int*   ei   = (const int*)  d_in[1];
    const int*   ct   = (const int*)  d_in[2];
    const float* Wq   = (const float*)d_in[3];
    const float* bq   = (const float*)d_in[4];
    const float* Wk   = (const float*)d_in[5];
    const float* bk   = (const float*)d_in[6];
    const float* Wv   = (const float*)d_in[7];
    const float* bv   = (const float*)d_in[8];
    const float* bio  = (const float*)d_in[9];
    const float* cemb = (const float*)d_in[10];
    const float* ipw  = (const float*)d_in[11];
    const float* ipb  = (const float*)d_in[12];
    const float* outw = (const float*)d_in[13];
    const float* outb = (const float*)d_in[14];

    float* out      = (float*)d_out;
    float* attended = out;                                    // [4096,512]
    float* attn     = out + (size_t)NN * ED;                  // [4096,4096]
    float* phase    = attn + (size_t)NN * NN;                 // [4096,512]
    float* coh      = phase + (size_t)NN * ED;                // scalar

    const int ne = in_sizes[1] / 2;
    const size_t NS = (size_t)NN * ED;

    float *Q0, *K0, *QKV, *qkv2, *og, *bioT, *rowent;
    unsigned* msk;
    cudaGetSymbolAddress((void**)&Q0,     g_Q0);
    cudaGetSymbolAddress((void**)&K0,     g_K0);
    cudaGetSymbolAddress((void**)&QKV,    g_QKV);
    cudaGetSymbolAddress((void**)&qkv2,   g_qkv2);
    cudaGetSymbolAddress((void**)&og,     g_o);
    cudaGetSymbolAddress((void**)&bioT,   g_bioT);
    cudaGetSymbolAddress((void**)&msk,    g_mask);
    cudaGetSymbolAddress((void**)&rowent, g_rowent);

    // edge mask
    zero_mask_kernel<<<(NN * MASKW) / 1024, 1024>>>(msk);
    build_mask_kernel<<<(ne + 255) / 256, 256>>>(ei, ne, msk);

    // bio^T for Q-side mixing
    transpose512_kernel<<<dim3(16, 16), dim3(32, 8)>>>(bio, bioT);

    // ---- Q/K chain feeding phase: EXACT fp32 (FFMA) ----
    sgemm_nt<EPI_BIAS><<<dim3(4, 32), 256>>>(nf, Wq, Q0, NN, ED, DIN, bq, nullptr, nullptr);
    sgemm_nt<EPI_BIAS><<<dim3(4, 32), 256>>>(nf, Wk, K0, NN, ED, DIN, bk, nullptr, nullptr);
    sgemm_nt<EPI_CE><<<dim3(4, 32), 256>>>(Q0, bioT, QKV, NN, ED, ED, nullptr, ct, cemb);
    sgemm_nt<EPI_CE><<<dim3(4, 32), 256>>>(K0, bio, QKV + NS, NN, ED, ED, nullptr, ct, cemb);

    // V projection (3xTF32, feeds only attended)
    gemm_tf32<64, 128, EPI_BIAS, true><<<dim3(4, 64), 256>>>(nf, 0, Wv, 0, QKV + 2 * NS, 0,
                                                             NN, ED, DIN,
                                                             bv, 0, nullptr, nullptr, nullptr, 0.f);

    // phase = atan2(Kf, Qf)  (exact inputs)
    phase_kernel<<<(NN * ED) / 1024, 1024>>>(QKV, QKV + NS, phase);

    // masked scores -> attn region (1xTF32):  Qf @ Kf^T / sqrt(512), -1e9 off-edge
    gemm_tf32<128, 128, EPI_MASK, false><<<dim3(32, 32), 256>>>(QKV, 0, QKV + NS, 0, attn, 0,
                                                                NN, NN, ED,
                                                                nullptr, 0, nullptr, nullptr, msk,
                                                                0.044194173824159216f);

    // row softmax in-place + per-row entropy, then coherence
    softmax_row_kernel<<<NN, 256>>>(attn, rowent);
    reduce_entropy_kernel<<<1, 1024>>>(rowent, coh);

    // in_proj (3xTF32, batched z=3): q/k/v = {Qf,Kf,V} @ ipw[z]^T + ipb[z]
    gemm_tf32<64, 128, EPI_BIAS, true><<<dim3(4, 64, 3), 256>>>(QKV, (long long)NS,
                                                                ipw, (long long)ED * ED,
                                                                qkv2, (long long)NS,
                                                                NN, ED, ED,
                                                                ipb, (long long)ED,
                                                                nullptr, nullptr, nullptr, 0.f);

    // flash MHA per head (tf32 tensor cores)
    const int mha_smem = (128 * QLD + 128 * PLD + 2 * KTS + 2 * VTS) * 4;
    cudaFuncSetAttribute(flash_mha_tf32, cudaFuncAttributeMaxDynamicSharedMemorySize, mha_smem);
    flash_mha_tf32<<<dim3(NN / 128, NHEAD), 256, mha_smem>>>(qkv2, qkv2 + NS, qkv2 + 2 * NS, og);

    // output projection (3xTF32)
    gemm_tf32<64, 128, EPI_BIAS, true><<<dim3(4, 64), 256>>>(og, 0, outw, 0, attended, 0,
                                                             NN, ED, ED,
                                                             outb, 0, nullptr, nullptr, nullptr, 0.f);
}

// round 9
// speedup vs baseline: 1.9531x; 1.0751x over previous
#include <cuda_runtime.h>
#include <math.h>
#include <stdint.h>

// ---------------------------------------------------------------------------
// Problem constants
// ---------------------------------------------------------------------------
#define NN 4096          // nodes
#define DIN 256          // input dim
#define ED 512           // quantum dim
#define NHEAD 8
#define HD 64
#define MASKW 128        // 4096/32 words per row

#define NEG_INF (__int_as_float(0xff800000))

// ---------------------------------------------------------------------------
// Scratch (device globals; no allocation allowed)
// ---------------------------------------------------------------------------
__device__ float    g_Q0[(size_t)NN * ED];
__device__ float    g_K0[(size_t)NN * ED];
__device__ float    g_QKV[(size_t)3 * NN * ED];   // Qfinal, Kfinal, V
__device__ float    g_qkv2[(size_t)3 * NN * ED];  // q, k, v after in_proj
__device__ float    g_o[(size_t)NN * ED];
__device__ float    g_bioT[(size_t)ED * ED];
__device__ unsigned g_mask[(size_t)NN * MASKW];
__device__ float    g_rowent[NN];

// ---------------------------------------------------------------------------
// Helpers
// ---------------------------------------------------------------------------
__device__ __forceinline__ float warp_red_sum(float v) {
#pragma unroll
    for (int o = 16; o; o >>= 1) v += __shfl_xor_sync(0xffffffffu, v, o);
    return v;
}
__device__ __forceinline__ float warp_red_max(float v) {
#pragma unroll
    for (int o = 16; o; o >>= 1) v = fmaxf(v, __shfl_xor_sync(0xffffffffu, v, o));
    return v;
}

__device__ __forceinline__ uint32_t f2tf32(float x) {
    uint32_t u;
    asm("cvt.rna.tf32.f32 %0, %1;" : "=r"(u) : "f"(x));
    return u;
}

__device__ __forceinline__ void mma8(float* c, const uint32_t* a, const uint32_t* b) {
    asm volatile(
        "mma.sync.aligned.m16n8k8.row.col.f32.tf32.tf32.f32 "
        "{%0,%1,%2,%3}, {%4,%5,%6,%7}, {%8,%9}, {%0,%1,%2,%3};"
        : "+f"(c[0]), "+f"(c[1]), "+f"(c[2]), "+f"(c[3])
        : "r"(a[0]), "r"(a[1]), "r"(a[2]), "r"(a[3]), "r"(b[0]), "r"(b[1]));
}

__device__ __forceinline__ void cp_async16(uint32_t saddr, const void* gaddr) {
    asm volatile("cp.async.cg.shared.global [%0], [%1], 16;" :: "r"(saddr), "l"(gaddr));
}
#define CP_COMMIT() asm volatile("cp.async.commit_group;" ::: "memory")
#define CP_WAIT0()  asm volatile("cp.async.wait_group 0;" ::: "memory")

// ---------------------------------------------------------------------------
// Mask build
// ---------------------------------------------------------------------------
__global__ void zero_mask_kernel(unsigned* __restrict__ m) {
    m[(size_t)blockIdx.x * 1024 + threadIdx.x] = 0u;
}

__global__ void build_mask_kernel(const int* __restrict__ ei, int ne,
                                  unsigned* __restrict__ m) {
    int idx = blockIdx.x * blockDim.x + threadIdx.x;
    if (idx < ne) {
        int r = ei[idx];
        int c = ei[ne + idx];
        atomicOr(&m[(size_t)r * MASKW + (c >> 5)], 1u << (c & 31));
    }
}

// ---------------------------------------------------------------------------
// 512x512 transpose (bio -> bioT)
// ---------------------------------------------------------------------------
__global__ void transpose512_kernel(const float* __restrict__ in, float* __restrict__ out) {
    __shared__ float tile[32][33];
    int bx = blockIdx.x * 32, by = blockIdx.y * 32;
    int tx = threadIdx.x, ty = threadIdx.y;
#pragma unroll
    for (int j = 0; j < 32; j += 8)
        tile[ty + j][tx] = in[(size_t)(by + ty + j) * ED + bx + tx];
    __syncthreads();
#pragma unroll
    for (int j = 0; j < 32; j += 8)
        out[(size_t)(bx + ty + j) * ED + by + tx] = tile[tx][ty + j];
}

// ---------------------------------------------------------------------------
// fp32 SGEMM (NT), exact: C[M,N] = A[M,K] * B[N,K]^T  (+ epilogue)
// Used ONLY for the Q/K chain feeding atan2-phase (zero precision budget).
// Double-buffered smem + register prefetch.
// ---------------------------------------------------------------------------
#define BM 128
#define BN 128
#define BK 16

enum { EPI_BIAS = 0, EPI_CE = 1, EPI_MASK = 2 };

template <int EPI>
__global__ void __launch_bounds__(256)
sgemm_nt(const float* __restrict__ A,
         const float* __restrict__ B,
         float* __restrict__ C,
         int M, int N, int K,
         const float* __restrict__ bias,
         const int* __restrict__ ct,
         const float* __restrict__ cemb)
{
    __shared__ float As[2][BK][BM];
    __shared__ float Bs[2][BK][BN];

    const int tid = threadIdx.x;
    const int tx = tid & 15, ty = tid >> 4;
    const int bm = blockIdx.y * BM, bn = blockIdx.x * BN;

    const int lrow = tid >> 2;
    const int lc4  = (tid & 3) * 4;

    float acc[8][8];
#pragma unroll
    for (int i = 0; i < 8; ++i)
#pragma unroll
        for (int j = 0; j < 8; ++j) acc[i][j] = 0.f;

    float4 pa[2], pb[2];

    auto ldg = [&](int k0) {
#pragma unroll
        for (int t = 0; t < 2; ++t) {
            int row = lrow + t * 64;
            pa[t] = *(const float4*)(A + (size_t)(bm + row) * K + k0 + lc4);
            pb[t] = *(const float4*)(B + (size_t)(bn + row) * K + k0 + lc4);
        }
    };
    auto sts = [&](int st) {
#pragma unroll
        for (int t = 0; t < 2; ++t) {
            int row = lrow + t * 64;
            As[st][lc4 + 0][row] = pa[t].x; As[st][lc4 + 1][row] = pa[t].y;
            As[st][lc4 + 2][row] = pa[t].z; As[st][lc4 + 3][row] = pa[t].w;
            Bs[st][lc4 + 0][row] = pb[t].x; Bs[st][lc4 + 1][row] = pb[t].y;
            Bs[st][lc4 + 2][row] = pb[t].z; Bs[st][lc4 + 3][row] = pb[t].w;
        }
    };

    ldg(0);
    sts(0);
    __syncthreads();

    const int nk = K / BK;
    int st = 0;
    for (int kt = 0; kt < nk; ++kt) {
        if (kt + 1 < nk) ldg((kt + 1) * BK);
#pragma unroll
        for (int kk = 0; kk < BK; ++kk) {
            float4 a0 = *(const float4*)&As[st][kk][ty * 8];
            float4 a1 = *(const float4*)&As[st][kk][ty * 8 + 4];
            float4 b0 = *(const float4*)&Bs[st][kk][tx * 8];
            float4 b1 = *(const float4*)&Bs[st][kk][tx * 8 + 4];
            float av[8] = {a0.x, a0.y, a0.z, a0.w, a1.x, a1.y, a1.z, a1.w};
            float bv[8] = {b0.x, b0.y, b0.z, b0.w, b1.x, b1.y, b1.z, b1.w};
#pragma unroll
            for (int i = 0; i < 8; ++i)
#pragma unroll
                for (int j = 0; j < 8; ++j)
                    acc[i][j] += av[i] * bv[j];
        }
        if (kt + 1 < nk) sts(st ^ 1);
        __syncthreads();
        st ^= 1;
    }

#pragma unroll
    for (int i = 0; i < 8; ++i) {
        int gm = bm + ty * 8 + i;
#pragma unroll
        for (int j = 0; j < 8; ++j) {
            int gn = bn + tx * 8 + j;
            float v = acc[i][j];
            if (EPI == EPI_BIAS) {
                v += bias[gn];
            } else {
                v += 0.1f * cemb[(size_t)ct[gm] * N + gn];
            }
            C[(size_t)gm * N + gn] = v;
        }
    }
}

// ---------------------------------------------------------------------------
// tf32 tensor-core GEMM (NT):  C[M,N] = A[M,K] * B[N,K]^T  (+ epilogue)
// SPLIT=true: 3xTF32 (near-fp32). SPLIT=false: single tf32, double-buffered.
// ---------------------------------------------------------------------------
template <int TBM, int TBN, int EPI, bool SPLIT>
__global__ void __launch_bounds__(256)
gemm_tf32(const float* __restrict__ A, long long sAz,
          const float* __restrict__ B, long long sBz,
          float* __restrict__ C, long long sCz,
          int M, int N, int K,
          const float* __restrict__ bias, long long sbz,
          const int* __restrict__ ct,
          const float* __restrict__ cemb,
          const unsigned* __restrict__ mask,
          float scale)
{
    constexpr int LDA = TBM + 8;
    constexpr int LDB = TBN + 8;
    constexpr int AF4 = (TBM * 16) / (4 * 256);
    constexpr int BF4 = (TBN * 16) / (4 * 256);
    constexpr int WM = TBM / 4, WN = TBN / 2;
    constexpr int MF = WM / 16, NF = WN / 8;
    constexpr int NC = SPLIT ? 2 : 1;
    constexpr int NBUF = SPLIT ? 1 : 2;

    __shared__ uint32_t As[NBUF][NC][16][LDA];
    __shared__ uint32_t Bs[NBUF][NC][16][LDB];

    A += (size_t)blockIdx.z * sAz;
    B += (size_t)blockIdx.z * sBz;
    C += (size_t)blockIdx.z * sCz;
    if (bias) bias += (size_t)blockIdx.z * sbz;

    const int tid = threadIdx.x;
    const int lane = tid & 31, wid = tid >> 5;
    const int wm = wid & 3, wn = wid >> 2;
    const int bm = blockIdx.y * TBM, bn = blockIdx.x * TBN;
    const int lq = lane >> 2, lr = lane & 3;

    float c[MF][NF][4];
#pragma unroll
    for (int i = 0; i < MF; ++i)
#pragma unroll
        for (int j = 0; j < NF; ++j)
#pragma unroll
            for (int r = 0; r < 4; ++r) c[i][j][r] = 0.f;

    float4 pa[AF4], pb[BF4];

    auto store_a = [&](int st) {
#pragma unroll
        for (int t = 0; t < AF4; ++t) {
            int f = tid + t * 256, m = f >> 2, k4 = (f & 3) * 4;
            float xs[4] = {pa[t].x, pa[t].y, pa[t].z, pa[t].w};
#pragma unroll
            for (int e = 0; e < 4; ++e) {
                uint32_t h = f2tf32(xs[e]);
                As[st][0][k4 + e][m] = h;
                if (SPLIT)
                    As[st][1][k4 + e][m] = f2tf32(xs[e] - __uint_as_float(h));
            }
        }
    };
    auto store_b = [&](int st) {
#pragma unroll
        for (int t = 0; t < BF4; ++t) {
            int f = tid + t * 256, n = f >> 2, k4 = (f & 3) * 4;
            float xs[4] = {pb[t].x, pb[t].y, pb[t].z, pb[t].w};
#pragma unroll
            for (int e = 0; e < 4; ++e) {
                uint32_t h = f2tf32(xs[e]);
                Bs[st][0][k4 + e][n] = h;
                if (SPLIT)
                    Bs[st][1][k4 + e][n] = f2tf32(xs[e] - __uint_as_float(h));
            }
        }
    };
    auto load_ab = [&](int k0) {
#pragma unroll
        for (int t = 0; t < AF4; ++t) {
            int f = tid + t * 256;
            pa[t] = *(const float4*)(A + (size_t)(bm + (f >> 2)) * K + k0 + (f & 3) * 4);
        }
#pragma unroll
        for (int t = 0; t < BF4; ++t) {
            int f = tid + t * 256;
            pb[t] = *(const float4*)(B + (size_t)(bn + (f >> 2)) * K + k0 + (f & 3) * 4);
        }
    };
    auto compute = [&](int st) {
#pragma unroll
        for (int ks = 0; ks < 16; ks += 8) {
            uint32_t af[MF][NC][4], bf[NF][NC][2];
#pragma unroll
            for (int i = 0; i < MF; ++i) {
                int m0 = wm * WM + i * 16;
#pragma unroll
                for (int cc = 0; cc < NC; ++cc) {
                    af[i][cc][0] = As[st][cc][ks + lr][m0 + lq];
                    af[i][cc][1] = As[st][cc][ks + lr][m0 + lq + 8];
                    af[i][cc][2] = As[st][cc][ks + lr + 4][m0 + lq];
                    af[i][cc][3] = As[st][cc][ks + lr + 4][m0 + lq + 8];
                }
            }
#pragma unroll
            for (int j = 0; j < NF; ++j) {
                int n0 = wn * WN + j * 8;
#pragma unroll
                for (int cc = 0; cc < NC; ++cc) {
                    bf[j][cc][0] = Bs[st][cc][ks + lr][n0 + lq];
                    bf[j][cc][1] = Bs[st][cc][ks + lr + 4][n0 + lq];
                }
            }
#pragma unroll
            for (int i = 0; i < MF; ++i)
#pragma unroll
                for (int j = 0; j < NF; ++j) {
                    mma8(c[i][j], af[i][0], bf[j][0]);
                    if (SPLIT) {
                        mma8(c[i][j], af[i][0], bf[j][1]);
                        mma8(c[i][j], af[i][1], bf[j][0]);
                    }
                }
        }
    };

    const int nk = K >> 4;

    if (!SPLIT) {
        load_ab(0);
        store_a(0); store_b(0);
        __syncthreads();
        int st = 0;
        for (int kt = 0; kt < nk; ++kt) {
            if (kt + 1 < nk) load_ab((kt + 1) << 4);
            compute(st);
            if (kt + 1 < nk) { store_a(st ^ 1); store_b(st ^ 1); }
            __syncthreads();
            st ^= 1;
        }
    } else {
        load_ab(0);
        store_a(0); store_b(0);
        __syncthreads();
        for (int kt = 0; kt < nk; ++kt) {
            if (kt + 1 < nk) load_ab((kt + 1) << 4);
            compute(0);
            __syncthreads();
            if (kt + 1 < nk) {
                store_a(0); store_b(0);
                __syncthreads();
            }
        }
    }

#pragma unroll
    for (int i = 0; i < MF; ++i) {
        int gm = bm + wm * WM + i * 16 + lq;
        int t0 = 0, t1 = 0;
        if (EPI == EPI_CE) { t0 = ct[gm]; t1 = ct[gm + 8]; }
#pragma unroll
        for (int j = 0; j < NF; ++j) {
            int gn = bn + wn * WN + j * 8 + lr * 2;
            float v00 = c[i][j][0], v01 = c[i][j][1];
            float v10 = c[i][j][2], v11 = c[i][j][3];
            if (EPI == EPI_BIAS) {
                float b0 = bias[gn], b1 = bias[gn + 1];
                v00 += b0; v01 += b1; v10 += b0; v11 += b1;
            } else if (EPI == EPI_CE) {
                v00 += 0.1f * cemb[(size_t)t0 * N + gn];
                v01 += 0.1f * cemb[(size_t)t0 * N + gn + 1];
                v10 += 0.1f * cemb[(size_t)t1 * N + gn];
                v11 += 0.1f * cemb[(size_t)t1 * N + gn + 1];
            } else {
                unsigned w0 = mask[(size_t)gm * MASKW + (gn >> 5)];
                unsigned w1 = mask[(size_t)(gm + 8) * MASKW + (gn >> 5)];
                v00 = ((w0 >> (gn & 31)) & 1u) ? v00 * scale : -1e9f;
                v01 = ((w0 >> ((gn + 1) & 31)) & 1u) ? v01 * scale : -1e9f;
                v10 = ((w1 >> (gn & 31)) & 1u) ? v10 * scale : -1e9f;
                v11 = ((w1 >> ((gn + 1) & 31)) & 1u) ? v11 * scale : -1e9f;
            }
            float2 r0 = {v00, v01}, r1 = {v10, v11};
            *(float2*)(C + (size_t)gm * N + gn) = r0;
            *(float2*)(C + (size_t)(gm + 8) * N + gn) = r1;
        }
    }
}

// ---------------------------------------------------------------------------
// phase = atan2(K, Q) elementwise
// ---------------------------------------------------------------------------
__global__ void phase_kernel(const float* __restrict__ Q, const float* __restrict__ K,
                             float* __restrict__ phase) {
    size_t i = (size_t)blockIdx.x * blockDim.x + threadIdx.x;
    phase[i] = atan2f(K[i], Q[i]);
}

// ---------------------------------------------------------------------------
// Row softmax over masked scores (in-place on attn region) + per-row entropy
// ---------------------------------------------------------------------------
__global__ void __launch_bounds__(256)
softmax_row_kernel(float* __restrict__ attn, float* __restrict__ row_ent) {
    __shared__ float red[8];
    __shared__ float bval;
    const int tid = threadIdx.x;
    const int wid = tid >> 5, lane = tid & 31;
    float* p = attn + (size_t)blockIdx.x * NN;

    float4 x[4];
#pragma unroll
    for (int t = 0; t < 4; ++t)
        x[t] = *(const float4*)(p + t * 1024 + tid * 4);

    float mx = NEG_INF;
#pragma unroll
    for (int t = 0; t < 4; ++t)
        mx = fmaxf(fmaxf(fmaxf(mx, x[t].x), fmaxf(x[t].y, x[t].z)), x[t].w);
    mx = warp_red_max(mx);
    if (lane == 0) red[wid] = mx;
    __syncthreads();
    if (wid == 0) {
        float v = (lane < 8) ? red[lane] : NEG_INF;
        v = warp_red_max(v);
        if (lane == 0) bval = v;
    }
    __syncthreads();
    mx = bval;
    __syncthreads();

    float e[16];
    float s = 0.f;
#pragma unroll
    for (int t = 0; t < 4; ++t) {
        e[t * 4 + 0] = __expf(x[t].x - mx);
        e[t * 4 + 1] = __expf(x[t].y - mx);
        e[t * 4 + 2] = __expf(x[t].z - mx);
        e[t * 4 + 3] = __expf(x[t].w - mx);
        s += e[t * 4 + 0] + e[t * 4 + 1] + e[t * 4 + 2] + e[t * 4 + 3];
    }
    s = warp_red_sum(s);
    if (lane == 0) red[wid] = s;
    __syncthreads();
    if (wid == 0) {
        float v = (lane < 8) ? red[lane] : 0.f;
        v = warp_red_sum(v);
        if (lane == 0) bval = v;
    }
    __syncthreads();
    const float inv = 1.0f / bval;
    __syncthreads();

    float ent = 0.f;
#pragma unroll
    for (int t = 0; t < 4; ++t) {
        float4 r;
        r.x = e[t * 4 + 0] * inv;
        r.y = e[t * 4 + 1] * inv;
        r.z = e[t * 4 + 2] * inv;
        r.w = e[t * 4 + 3] * inv;
        ent += r.x * logf(r.x + 1e-10f) + r.y * logf(r.y + 1e-10f)
             + r.z * logf(r.z + 1e-10f) + r.w * logf(r.w + 1e-10f);
        *(float4*)(p + t * 1024 + tid * 4) = r;
    }
    ent = warp_red_sum(ent);
    if (lane == 0) red[wid] = ent;
    __syncthreads();
    if (wid == 0) {
        float v = (lane < 8) ? red[lane] : 0.f;
        v = warp_red_sum(v);
        if (lane == 0) row_ent[blockIdx.x] = v;
    }
}

__global__ void reduce_entropy_kernel(const float* __restrict__ row_ent,
                                      float* __restrict__ coh) {
    __shared__ float red[32];
    int tid = threadIdx.x, lane = tid & 31, wid = tid >> 5;
    float v = row_ent[tid] + row_ent[tid + 1024] + row_ent[tid + 2048] + row_ent[tid + 3072];
    v = warp_red_sum(v);
    if (lane == 0) red[wid] = v;
    __syncthreads();
    if (wid == 0) {
        float s = red[lane];
        s = warp_red_sum(s);
        if (lane == 0) {
            float entropy = -s;
            *coh = 1.0f - entropy / logf((float)NN);
        }
    }
}

// ---------------------------------------------------------------------------
// Flash MHA on tf32 tensor cores: softmax(q k^T / 8) v, per head.
// v2: P reuses the Q staging buffer (Q fragments are register-resident),
// K/V loaded via cp.async.cg as RAW fp32 bits consumed directly by the tf32
// mma (truncation; only feeds `attended`, which has ~4x error margin).
// Smem 112 KB -> 2 CTAs/SM -> grid 256 fits in ONE wave on 148 SMs.
// ---------------------------------------------------------------------------
#define PLD 76
#define KLD 76
#define VLD 72
#define KTS (64 * KLD)
#define VTS (64 * VLD)

__global__ void __launch_bounds__(256, 2)
flash_mha_tf32(const float* __restrict__ q, const float* __restrict__ k,
               const float* __restrict__ v, float* __restrict__ o)
{
    extern __shared__ uint32_t sm[];
    uint32_t* Pn = sm;                    // [128][PLD]  (Q staging, then P)
    uint32_t* Ks = Pn + 128 * PLD;        // [2][64][KLD] raw fp32 bits
    uint32_t* Vs = Ks + 2 * KTS;          // [2][64][VLD] raw fp32 bits

    const int tid = threadIdx.x;
    const int lane = tid & 31, wid = tid >> 5;
    const int lq = lane >> 2, lr = lane & 3;
    const int qbase = blockIdx.x * 128;
    const int hoff = blockIdx.y * HD;
    const int m0 = wid * 16;

    const uint32_t ks_base = (uint32_t)__cvta_generic_to_shared(Ks);
    const uint32_t vs_base = (uint32_t)__cvta_generic_to_shared(Vs);

    // Q -> smem staging [row][d], tf32 RN, pre-scaled by exact 1/8
#pragma unroll
    for (int t = 0; t < 8; ++t) {
        int f = tid + t * 256;                  // 0..2047 float4s
        int row = f >> 4, c4 = (f & 15) * 4;
        float4 val = *(const float4*)(q + (size_t)(qbase + row) * ED + hoff + c4);
        Pn[row * PLD + c4 + 0] = f2tf32(0.125f * val.x);
        Pn[row * PLD + c4 + 1] = f2tf32(0.125f * val.y);
        Pn[row * PLD + c4 + 2] = f2tf32(0.125f * val.z);
        Pn[row * PLD + c4 + 3] = f2tf32(0.125f * val.w);
    }
    __syncthreads();

    // Q fragments to registers
    uint32_t qa[8][4];
#pragma unroll
    for (int ks = 0; ks < 8; ++ks) {
        qa[ks][0] = Pn[(m0 + lq) * PLD + ks * 8 + lr];
        qa[ks][1] = Pn[(m0 + lq + 8) * PLD + ks * 8 + lr];
        qa[ks][2] = Pn[(m0 + lq) * PLD + ks * 8 + lr + 4];
        qa[ks][3] = Pn[(m0 + lq + 8) * PLD + ks * 8 + lr + 4];
    }

    auto prefetch = [&](int kt, int stg) {
        const float* kg = k + (size_t)(kt * 64) * ED + hoff;
        const float* vg = v + (size_t)(kt * 64) * ED + hoff;
        uint32_t kb = ks_base + (uint32_t)(stg * KTS) * 4u;
        uint32_t vb = vs_base + (uint32_t)(stg * VTS) * 4u;
#pragma unroll
        for (int t = 0; t < 4; ++t) {
            int f = tid + t * 256;              // 0..1023 float4s
            int row = f >> 4, c4 = (f & 15) * 4;
            cp_async16(kb + (uint32_t)(row * KLD + c4) * 4u, kg + (size_t)row * ED + c4);
            cp_async16(vb + (uint32_t)(row * VLD + c4) * 4u, vg + (size_t)row * ED + c4);
        }
    };

    float m_i[2] = {NEG_INF, NEG_INF};
    float l_i[2] = {0.f, 0.f};
    float oacc[8][4];
#pragma unroll
    for (int j = 0; j < 8; ++j)
#pragma unroll
        for (int r = 0; r < 4; ++r) oacc[j][r] = 0.f;

    prefetch(0, 0);
    CP_COMMIT();
    CP_WAIT0();
    __syncthreads();   // stage 0 ready; also orders Q-fragment reads before P writes

    int st = 0;
    for (int kt = 0; kt < NN / 64; ++kt) {
        if (kt + 1 < NN / 64) { prefetch(kt + 1, st ^ 1); CP_COMMIT(); }

        const uint32_t* kb = Ks + st * KTS;
        const uint32_t* vb = Vs + st * VTS;

        // S = Q K^T (scale folded into Q)
        float s[8][4];
#pragma unroll
        for (int j = 0; j < 8; ++j)
#pragma unroll
            for (int r = 0; r < 4; ++r) s[j][r] = 0.f;

#pragma unroll
        for (int ks = 0; ks < 8; ++ks) {
            uint32_t bf[8][2];
#pragma unroll
            for (int j = 0; j < 8; ++j) {
                bf[j][0] = kb[(j * 8 + lq) * KLD + ks * 8 + lr];
                bf[j][1] = kb[(j * 8 + lq) * KLD + ks * 8 + lr + 4];
            }
#pragma unroll
            for (int j = 0; j < 8; ++j)
                mma8(s[j], qa[ks], bf[j]);
        }

        // online softmax; rows lq (r0,r1) and lq+8 (r2,r3)
        float mx0 = NEG_INF, mx1 = NEG_INF;
#pragma unroll
        for (int j = 0; j < 8; ++j) {
            mx0 = fmaxf(mx0, fmaxf(s[j][0], s[j][1]));
            mx1 = fmaxf(mx1, fmaxf(s[j][2], s[j][3]));
        }
        mx0 = fmaxf(mx0, __shfl_xor_sync(0xffffffffu, mx0, 1));
        mx0 = fmaxf(mx0, __shfl_xor_sync(0xffffffffu, mx0, 2));
        mx1 = fmaxf(mx1, __shfl_xor_sync(0xffffffffu, mx1, 1));
        mx1 = fmaxf(mx1, __shfl_xor_sync(0xffffffffu, mx1, 2));

        float mn0 = fmaxf(m_i[0], mx0), mn1 = fmaxf(m_i[1], mx1);
        float c0 = __expf(m_i[0] - mn0), c1 = __expf(m_i[1] - mn1);
        m_i[0] = mn0; m_i[1] = mn1;

        float ls0 = 0.f, ls1 = 0.f;
#pragma unroll
        for (int j = 0; j < 8; ++j) {
            float p0 = __expf(s[j][0] - mn0);
            float p1 = __expf(s[j][1] - mn0);
            float p2 = __expf(s[j][2] - mn1);
            float p3 = __expf(s[j][3] - mn1);
            ls0 += p0 + p1;
            ls1 += p2 + p3;
            Pn[(m0 + lq) * PLD + j * 8 + 2 * lr]     = f2tf32(p0);
            Pn[(m0 + lq) * PLD + j * 8 + 2 * lr + 1] = f2tf32(p1);
            Pn[(m0 + lq + 8) * PLD + j * 8 + 2 * lr]     = f2tf32(p2);
            Pn[(m0 + lq + 8) * PLD + j * 8 + 2 * lr + 1] = f2tf32(p3);
        }
        ls0 += __shfl_xor_sync(0xffffffffu, ls0, 1);
        ls0 += __shfl_xor_sync(0xffffffffu, ls0, 2);
        ls1 += __shfl_xor_sync(0xffffffffu, ls1, 1);
        ls1 += __shfl_xor_sync(0xffffffffu, ls1, 2);
        l_i[0] = l_i[0] * c0 + ls0;
        l_i[1] = l_i[1] * c1 + ls1;

#pragma unroll
        for (int j = 0; j < 8; ++j) {
            oacc[j][0] *= c0; oacc[j][1] *= c0;
            oacc[j][2] *= c1; oacc[j][3] *= c1;
        }
        __syncwarp();

        // O += P V
#pragma unroll
        for (int ks = 0; ks < 8; ++ks) {
            uint32_t pa4[4];
            pa4[0] = Pn[(m0 + lq) * PLD + ks * 8 + lr];
            pa4[1] = Pn[(m0 + lq + 8) * PLD + ks * 8 + lr];
            pa4[2] = Pn[(m0 + lq) * PLD + ks * 8 + lr + 4];
            pa4[3] = Pn[(m0 + lq + 8) * PLD + ks * 8 + lr + 4];
            uint32_t bf[8][2];
#pragma unroll
            for (int j = 0; j < 8; ++j) {
                bf[j][0] = vb[(ks * 8 + lr) * VLD + j * 8 + lq];
                bf[j][1] = vb[(ks * 8 + lr + 4) * VLD + j * 8 + lq];
            }
#pragma unroll
            for (int j = 0; j < 8; ++j)
                mma8(oacc[j], pa4, bf[j]);
        }

        if (kt + 1 < NN / 64) CP_WAIT0();
        __syncthreads();
        st ^= 1;
    }

    // normalize + store
    float inv0 = 1.0f / l_i[0], inv1 = 1.0f / l_i[1];
#pragma unroll
    for (int j = 0; j < 8; ++j) {
        float2 r0 = {oacc[j][0] * inv0, oacc[j][1] * inv0};
        float2 r1 = {oacc[j][2] * inv1, oacc[j][3] * inv1};
        *(float2*)(o + (size_t)(qbase + m0 + lq) * ED + hoff + j * 8 + 2 * lr) = r0;
        *(float2*)(o + (size_t)(qbase + m0 + lq + 8) * ED + hoff + j * 8 + 2 * lr) = r1;
    }
}

// ---------------------------------------------------------------------------
// Host launcher
// ---------------------------------------------------------------------------
extern "C" void kernel_launch(void* const* d_in, const int* in_sizes, int n_in,
                              void* d_out, int out_size)
{
    const float* nf   = (const float*)d_in[0];
    const int*   ei   = (const int*)  d_in[1];
    const int*   ct   = (const int*)  d_in[2];
    const float* Wq   = (const float*)d_in[3];
    const float* bq   = (const float*)d_in[4];
    const float* Wk   = (const float*)d_in[5];
    const float* bk   = (const float*)d_in[6];
    const float* Wv   = (const float*)d_in[7];
    const float* bv   = (const float*)d_in[8];
    const float* bio  = (const float*)d_in[9];
    const float* cemb = (const float*)d_in[10];
    const float* ipw  = (const float*)d_in[11];
    const float* ipb  = (const float*)d_in[12];
    const float* outw = (const float*)d_in[13];
    const float* outb = (const float*)d_in[14];

    float* out      = (float*)d_out;
    float* attended = out;                                    // [4096,512]
    float* attn     = out + (size_t)NN * ED;                  // [4096,4096]
    float* phase    = attn + (size_t)NN * NN;                 // [4096,512]
    float* coh      = phase + (size_t)NN * ED;                // scalar

    const int ne = in_sizes[1] / 2;
    const size_t NS = (size_t)NN * ED;

    float *Q0, *K0, *QKV, *qkv2, *og, *bioT, *rowent;
    unsigned* msk;
    cudaGetSymbolAddress((void**)&Q0,     g_Q0);
    cudaGetSymbolAddress((void**)&K0,     g_K0);
    cudaGetSymbolAddress((void**)&QKV,    g_QKV);
    cudaGetSymbolAddress((void**)&qkv2,   g_qkv2);
    cudaGetSymbolAddress((void**)&og,     g_o);
    cudaGetSymbolAddress((void**)&bioT,   g_bioT);
    cudaGetSymbolAddress((void**)&msk,    g_mask);
    cudaGetSymbolAddress((void**)&rowent, g_rowent);

    // edge mask
    zero_mask_kernel<<<(NN * MASKW) / 1024, 1024>>>(msk);
    build_mask_kernel<<<(ne + 255) / 256, 256>>>(ei, ne, msk);

    // bio^T for Q-side mixing
    transpose512_kernel<<<dim3(16, 16), dim3(32, 8)>>>(bio, bioT);

    // ---- Q/K chain feeding phase: EXACT fp32 (FFMA), double-buffered ----
    sgemm_nt<EPI_BIAS><<<dim3(4, 32), 256>>>(nf, Wq, Q0, NN, ED, DIN, bq, nullptr, nullptr);
    sgemm_nt<EPI_BIAS><<<dim3(4, 32), 256>>>(nf, Wk, K0, NN, ED, DIN, bk, nullptr, nullptr);
    sgemm_nt<EPI_CE><<<dim3(4, 32), 256>>>(Q0, bioT, QKV, NN, ED, ED, nullptr, ct, cemb);
    sgemm_nt<EPI_CE><<<dim3(4, 32), 256>>>(K0, bio, QKV + NS, NN, ED, ED, nullptr, ct, cemb);

    // V projection (3xTF32, feeds only attended)
    gemm_tf32<64, 128, EPI_BIAS, true><<<dim3(4, 64), 256>>>(nf, 0, Wv, 0, QKV + 2 * NS, 0,
                                                             NN, ED, DIN,
                                                             bv, 0, nullptr, nullptr, nullptr, 0.f);

    // phase = atan2(Kf, Qf)  (exact inputs)
    phase_kernel<<<(NN * ED) / 1024, 1024>>>(QKV, QKV + NS, phase);

    // masked scores -> attn region (1xTF32):  Qf @ Kf^T / sqrt(512), -1e9 off-edge
    gemm_tf32<128, 128, EPI_MASK, false><<<dim3(32, 32), 256>>>(QKV, 0, QKV + NS, 0, attn, 0,
                                                                NN, NN, ED,
                                                                nullptr, 0, nullptr, nullptr, msk,
                                                                0.044194173824159216f);

    // row softmax in-place + per-row entropy, then coherence
    softmax_row_kernel<<<NN, 256>>>(attn, rowent);
    reduce_entropy_kernel<<<1, 1024>>>(rowent, coh);

    // in_proj (3xTF32, batched z=3): q/k/v = {Qf,Kf,V} @ ipw[z]^T + ipb[z]
    gemm_tf32<64, 128, EPI_BIAS, true><<<dim3(4, 64, 3), 256>>>(QKV, (long long)NS,
                                                                ipw, (long long)ED * ED,
                                                                qkv2, (long long)NS,
                                                                NN, ED, ED,
                                                                ipb, (long long)ED,
                                                                nullptr, nullptr, nullptr, 0.f);

    // flash MHA per head (tf32 tensor cores, cp.async, 2 CTA/SM)
    const int mha_smem = (128 * PLD + 2 * KTS + 2 * VTS) * 4;   // 114688 B
    cudaFuncSetAttribute(flash_mha_tf32, cudaFuncAttributeMaxDynamicSharedMemorySize, mha_smem);
    flash_mha_tf32<<<dim3(NN / 128, NHEAD), 256, mha_smem>>>(qkv2, qkv2 + NS, qkv2 + 2 * NS, og);

    // output projection (3xTF32)
    gemm_tf32<64, 128, EPI_BIAS, true><<<dim3(4, 64), 256>>>(og, 0, outw, 0, attended, 0,
                                                             NN, ED, ED,
                                                             outb, 0, nullptr, nullptr, nullptr, 0.f);
}